// round 5
// baseline (speedup 1.0000x reference)
#include <cuda_runtime.h>
#include <cuda_bf16.h>

#define BBATCH 16
#define NNODE  2048
#define CDIM   64
#define HDIM   128
#define KNEIGH 16
#define NT     (BBATCH*NNODE)        /* 32768 nodes  */
#define EDGES  (NT*KNEIGH)           /* 524288 edges */
#define BN_EPS 1e-5f
#define LDW    132                   /* smem tile pitch (floats): 16B-aligned, 4-way max conflicts */
#define TKBINS 4096

typedef unsigned long long ull;

// ---------------------------------------------------------------------------
// Static device scratch (no runtime allocation allowed)
// ---------------------------------------------------------------------------
__device__ float g_sq[NT];
__device__ float g_d2[(size_t)BBATCH * NNODE * NNODE];        // 256 MB
__device__ int   g_idx[EDGES];                                 // global neighbor idx
__device__ float g_p[2][(size_t)NT * HDIM];
__device__ float g_q[2][(size_t)NT * HDIM];
__device__ float g_bn1_sum[2][HDIM], g_bn1_sq[2][HDIM];
__device__ float g_a1[2][HDIM], g_c1[2][HDIM];
__device__ float g_aggmax[2][(size_t)NT * HDIM];
__device__ float g_aggmin[2][(size_t)NT * HDIM];
__device__ float g_bn2_sum[2][HDIM], g_bn2_sq[2][HDIM];
__device__ float g_a2[2][HDIM], g_c2[2][HDIM];
__device__ float g_hF[(size_t)NT * HDIM];
__device__ float g_bnF_sum[HDIM], g_bnF_sq[HDIM];
__device__ float g_aF[HDIM], g_cF[HDIM];

// ---------------------------------------------------------------------------
// f32x2 packed-FMA helpers (sm_100+ PTX; FFMA2 is PTX-only per SASS quickref)
// ---------------------------------------------------------------------------
__device__ __forceinline__ ull pk2(float lo, float hi) {
    ull r; asm("mov.b64 %0, {%1, %2};" : "=l"(r) : "f"(lo), "f"(hi)); return r;
}
__device__ __forceinline__ void fma2(ull &d, ull a, ull b) {
    asm("fma.rn.f32x2 %0, %1, %2, %0;" : "+l"(d) : "l"(a), "l"(b));
}
__device__ __forceinline__ float2 up2(ull v) {
    float2 f; asm("mov.b64 {%0, %1}, %2;" : "=f"(f.x), "=f"(f.y) : "l"(v)); return f;
}

// 8x8 micro-tile step: A k-major [kk][row], B k-major [kk][col], acc packed pairs along cols
__device__ __forceinline__ void micro_step(const float* __restrict__ Arow,
                                           const float* __restrict__ Brow,
                                           int ty8, int tx8, ull acc[8][4]) {
    float4 a0 = *(const float4*)(Arow + ty8);
    float4 a1 = *(const float4*)(Arow + ty8 + 4);
    float4 b0 = *(const float4*)(Brow + tx8);
    float4 b1 = *(const float4*)(Brow + tx8 + 4);
    ull bv0 = pk2(b0.x, b0.y), bv1 = pk2(b0.z, b0.w);
    ull bv2 = pk2(b1.x, b1.y), bv3 = pk2(b1.z, b1.w);
    float av[8] = {a0.x, a0.y, a0.z, a0.w, a1.x, a1.y, a1.z, a1.w};
#pragma unroll
    for (int i = 0; i < 8; i++) {
        ull ai = pk2(av[i], av[i]);
        fma2(acc[i][0], ai, bv0);
        fma2(acc[i][1], ai, bv1);
        fma2(acc[i][2], ai, bv2);
        fma2(acc[i][3], ai, bv3);
    }
}

__device__ __forceinline__ void unpack_acc(ull acc[8][4], float outv[8][8]) {
#pragma unroll
    for (int i = 0; i < 8; i++)
#pragma unroll
        for (int j2 = 0; j2 < 4; j2++) {
            float2 u = up2(acc[i][j2]);
            outv[i][2*j2]   = u.x;
            outv[i][2*j2+1] = u.y;
        }
}

// ---------------------------------------------------------------------------
// 0: zero accumulators (must run every launch: graph replays reuse globals)
// ---------------------------------------------------------------------------
__global__ void k_zero() {
    int t = threadIdx.x;
    if (t < HDIM) {
        g_bn1_sum[0][t] = 0.f; g_bn1_sum[1][t] = 0.f;
        g_bn1_sq[0][t]  = 0.f; g_bn1_sq[1][t]  = 0.f;
        g_bn2_sum[0][t] = 0.f; g_bn2_sum[1][t] = 0.f;
        g_bn2_sq[0][t]  = 0.f; g_bn2_sq[1][t]  = 0.f;
        g_bnF_sum[t]    = 0.f; g_bnF_sq[t]     = 0.f;
    }
}

// ---------------------------------------------------------------------------
// 1: per-node squared norms (one warp per node)
// ---------------------------------------------------------------------------
__global__ void k_sq(const float* __restrict__ x) {
    int w    = (blockIdx.x * blockDim.x + threadIdx.x) >> 5;
    int lane = threadIdx.x & 31;
    if (w >= NT) return;
    float v0 = x[(size_t)w * CDIM + lane];
    float v1 = x[(size_t)w * CDIM + 32 + lane];
    float s = v0 * v0 + v1 * v1;
#pragma unroll
    for (int off = 16; off; off >>= 1) s += __shfl_xor_sync(0xffffffffu, s, off);
    if (lane == 0) g_sq[w] = s;
}

// ---------------------------------------------------------------------------
// 2: pairwise squared distances per batch (128x128x64 tiles)
// ---------------------------------------------------------------------------
__global__ __launch_bounds__(256) void k_d2(const float* __restrict__ x) {
    __shared__ float Ai[32][LDW];
    __shared__ float Aj[32][LDW];
    const int b  = blockIdx.z;
    const int i0 = blockIdx.y * 128, j0 = blockIdx.x * 128;
    const float* X = x + (size_t)b * NNODE * CDIM;
    const int tid = threadIdx.x, ty = tid >> 4, tx = tid & 15;
    ull acc[8][4];
#pragma unroll
    for (int i = 0; i < 8; i++)
#pragma unroll
        for (int j = 0; j < 4; j++) acc[i][j] = 0ull;

    for (int kc = 0; kc < CDIM; kc += 32) {
        __syncthreads();
        for (int idx = tid; idx < 128 * 32; idx += 256) {
            int row = idx >> 5, kk = idx & 31;
            Ai[kk][row] = X[(size_t)(i0 + row) * CDIM + kc + kk];
            Aj[kk][row] = X[(size_t)(j0 + row) * CDIM + kc + kk];
        }
        __syncthreads();
#pragma unroll 8
        for (int kk = 0; kk < 32; kk++)
            micro_step(&Ai[kk][0], &Aj[kk][0], ty * 8, tx * 8, acc);
    }
    float outv[8][8];
    unpack_acc(acc, outv);
    float sqi[8], sqj[8];
#pragma unroll
    for (int i = 0; i < 8; i++) sqi[i] = g_sq[b * NNODE + i0 + ty * 8 + i];
#pragma unroll
    for (int j = 0; j < 8; j++) sqj[j] = g_sq[b * NNODE + j0 + tx * 8 + j];
#pragma unroll
    for (int i = 0; i < 8; i++) {
        size_t row = ((size_t)(b * NNODE + i0 + ty * 8 + i)) * NNODE + j0 + tx * 8;
        float v[8];
#pragma unroll
        for (int j = 0; j < 8; j++) v[j] = sqi[i] + sqj[j] - 2.f * outv[i][j];
        *(float4*)&g_d2[row]     = make_float4(v[0], v[1], v[2], v[3]);
        *(float4*)&g_d2[row + 4] = make_float4(v[4], v[5], v[6], v[7]);
    }
}

// ---------------------------------------------------------------------------
// 3: top-K smallest per row via 12-bit radix select + tiny candidate argmin
// ---------------------------------------------------------------------------
__device__ __forceinline__ unsigned d2key(float v) {
    unsigned u = __float_as_uint(v);
    return (u & 0x80000000u) ? ~u : (u | 0x80000000u);   // order-preserving
}

__global__ __launch_bounds__(256) void k_topk() {
    __shared__ float vals[NNODE];          // 8KB  row cache
    __shared__ int   hist[TKBINS];         // 16KB
    __shared__ float cval[NNODE];          // 8KB  candidates (worst-case full row)
    __shared__ int   cidx[NNODE];          // 8KB
    __shared__ int   wtot[8];
    __shared__ int   s_binB, s_nc;
    __shared__ float s_wv[8];
    __shared__ int   s_wi[8], s_wc[8];

    const size_t rowoff = (size_t)blockIdx.x * NNODE;
    const int tid  = threadIdx.x;
    const int lane = tid & 31, warp = tid >> 5;
    const int b = blockIdx.x >> 11;   // NNODE = 2048

    for (int i = tid; i < TKBINS; i += 256) hist[i] = 0;
    __syncthreads();

    // Pass A: load row + histogram top-12-bit keys
#pragma unroll
    for (int jj = 0; jj < 8; jj++) {
        int j = tid + jj * 256;
        float v = g_d2[rowoff + j];
        vals[j] = v;
        atomicAdd(&hist[d2key(v) >> 20], 1);
    }
    __syncthreads();

    // Block scan over 4096 bins: per-thread group of 16, warp scan, serial warp offsets
    int g = 0;
#pragma unroll
    for (int i = 0; i < 16; i++) g += hist[tid * 16 + i];
    int inc = g;
#pragma unroll
    for (int off = 1; off < 32; off <<= 1) {
        int n = __shfl_up_sync(0xffffffffu, inc, off);
        if (lane >= off) inc += n;
    }
    if (lane == 31) wtot[warp] = inc;
    __syncthreads();
    if (tid == 0) {
        int a = 0;
#pragma unroll
        for (int w = 0; w < 8; w++) { int t = wtot[w]; wtot[w] = a; a += t; }
    }
    __syncthreads();
    int pre = wtot[warp] + inc - g;   // exclusive prefix before this thread's 16 bins
    {
        int running = pre;
#pragma unroll
        for (int i = 0; i < 16; i++) {
            int c = hist[tid * 16 + i];
            if (running < KNEIGH && running + c >= KNEIGH) s_binB = tid * 16 + i;
            running += c;
        }
    }
    if (tid == 0) s_nc = 0;
    __syncthreads();

    // Pass B: collect candidates with bin <= B
    const int B = s_binB;
#pragma unroll
    for (int jj = 0; jj < 8; jj++) {
        int j = tid + jj * 256;
        float v = vals[j];
        if ((int)(d2key(v) >> 20) <= B) {
            int p = atomicAdd(&s_nc, 1);
            cval[p] = v; cidx[p] = j;
        }
    }
    __syncthreads();
    const int nc = s_nc;

    // K x argmin over the (small) candidate set; tie-break smallest index
    for (int k = 0; k < KNEIGH; k++) {
        float bv = 3.0e38f; int bi = 0x7fffffff, bc = -1;
        for (int c = tid; c < nc; c += 256) {
            float v = cval[c]; int id = cidx[c];
            if (v < bv || (v == bv && id < bi)) { bv = v; bi = id; bc = c; }
        }
#pragma unroll
        for (int off = 16; off; off >>= 1) {
            float ov = __shfl_down_sync(0xffffffffu, bv, off);
            int   oi = __shfl_down_sync(0xffffffffu, bi, off);
            int   oc = __shfl_down_sync(0xffffffffu, bc, off);
            if (ov < bv || (ov == bv && oi < bi)) { bv = ov; bi = oi; bc = oc; }
        }
        if (lane == 0) { s_wv[warp] = bv; s_wi[warp] = bi; s_wc[warp] = bc; }
        __syncthreads();
        if (tid == 0) {
            float fv = s_wv[0]; int fi = s_wi[0], fc = s_wc[0];
#pragma unroll
            for (int w = 1; w < 8; w++)
                if (s_wv[w] < fv || (s_wv[w] == fv && s_wi[w] < fi)) { fv = s_wv[w]; fi = s_wi[w]; fc = s_wc[w]; }
            g_idx[(size_t)blockIdx.x * KNEIGH + k] = b * NNODE + fi;
            cval[fc] = 3.0e38f;
        }
        __syncthreads();
    }
}

// ---------------------------------------------------------------------------
// 4: p/q GEMMs. z: 0=s/p, 1=s/q, 2=t/p, 3=t/q
// ---------------------------------------------------------------------------
__global__ __launch_bounds__(256) void k_pq(const float* __restrict__ x,
                                            const float* __restrict__ sW1, const float* __restrict__ sb1,
                                            const float* __restrict__ tW1, const float* __restrict__ tb1) {
    __shared__ float Xs[32][LDW];
    __shared__ float Ws[32][LDW];
    const int z   = blockIdx.z;
    const int st  = z >> 1;
    const bool isP = (z & 1) == 0;
    const float* W1 = st ? tW1 : sW1;
    const float* B1 = st ? tb1 : sb1;
    const int n0 = blockIdx.x * 128;
    const int tid = threadIdx.x, ty = tid >> 4, tx = tid & 15;
    ull acc[8][4];
#pragma unroll
    for (int i = 0; i < 8; i++)
#pragma unroll
        for (int j = 0; j < 4; j++) acc[i][j] = 0ull;

    for (int kc = 0; kc < CDIM; kc += 32) {
        __syncthreads();
        for (int idx = tid; idx < 128 * 32; idx += 256) {
            int r = idx >> 5, kk = idx & 31;
            Xs[kk][r] = x[(size_t)(n0 + r) * CDIM + kc + kk];
        }
        for (int idx = tid; idx < 32 * HDIM; idx += 256) {
            int kk = idx >> 7, col = idx & 127;
            int kr = kc + kk;
            float w = W1[(size_t)(CDIM + kr) * HDIM + col];
            if (isP) w = W1[(size_t)kr * HDIM + col] - w;
            Ws[kk][col] = w;
        }
        __syncthreads();
#pragma unroll 8
        for (int kk = 0; kk < 32; kk++)
            micro_step(&Xs[kk][0], &Ws[kk][0], ty * 8, tx * 8, acc);
    }
    float outv[8][8];
    unpack_acc(acc, outv);
    float* O = isP ? g_p[st] : g_q[st];
    float bj[8];
#pragma unroll
    for (int j = 0; j < 8; j++) bj[j] = isP ? B1[tx * 8 + j] : 0.f;
#pragma unroll
    for (int i = 0; i < 8; i++) {
        size_t row = (size_t)(n0 + ty * 8 + i) * HDIM + tx * 8;
        *(float4*)&O[row]     = make_float4(outv[i][0] + bj[0], outv[i][1] + bj[1],
                                            outv[i][2] + bj[2], outv[i][3] + bj[3]);
        *(float4*)&O[row + 4] = make_float4(outv[i][4] + bj[4], outv[i][5] + bj[5],
                                            outv[i][6] + bj[6], outv[i][7] + bj[7]);
    }
}

// ---------------------------------------------------------------------------
// 5: BN1 statistics over all edges, both streams (h1 = p[n] + q[j])
// ---------------------------------------------------------------------------
__global__ void k_bn1stats() {
    const int h = threadIdx.x;          // 128 threads = channels
    const int node0 = blockIdx.x * 32;  // 1024 blocks x 32 nodes
    float s0 = 0.f, q0 = 0.f, s1 = 0.f, q1 = 0.f;
    for (int nl = 0; nl < 32; nl++) {
        int n = node0 + nl;
        float p0 = g_p[0][(size_t)n * HDIM + h];
        float p1 = g_p[1][(size_t)n * HDIM + h];
        for (int k = 0; k < KNEIGH; k++) {
            int j = g_idx[(size_t)n * KNEIGH + k];
            float a = p0 + g_q[0][(size_t)j * HDIM + h];
            float b = p1 + g_q[1][(size_t)j * HDIM + h];
            s0 += a; q0 += a * a;
            s1 += b; q1 += b * b;
        }
    }
    atomicAdd(&g_bn1_sum[0][h], s0); atomicAdd(&g_bn1_sq[0][h], q0);
    atomicAdd(&g_bn1_sum[1][h], s1); atomicAdd(&g_bn1_sq[1][h], q1);
}

// ---------------------------------------------------------------------------
// 6: BN finalize -> per-channel affine (a, c). which: 0=bn1, 1=bn2, 2=bnF
// ---------------------------------------------------------------------------
__global__ void k_bnfin(int which, int st, const float* __restrict__ g,
                        const float* __restrict__ be, float invN) {
    int h = threadIdx.x;
    float s, q;
    if (which == 0)      { s = g_bn1_sum[st][h]; q = g_bn1_sq[st][h]; }
    else if (which == 1) { s = g_bn2_sum[st][h]; q = g_bn2_sq[st][h]; }
    else                 { s = g_bnF_sum[h];     q = g_bnF_sq[h]; }
    float m   = s * invN;
    float var = fmaxf(q * invN - m * m, 0.f);
    float a   = g[h] * rsqrtf(var + BN_EPS);
    float c   = be[h] - m * a;
    if (which == 0)      { g_a1[st][h] = a; g_c1[st][h] = c; }
    else if (which == 1) { g_a2[st][h] = a; g_c2[st][h] = c; }
    else                 { g_aF[h] = a;     g_cF[h] = c; }
}

// ---------------------------------------------------------------------------
// 7: edge GEMM: z = relu(bn1(h1)), h2 = z @ W2 + b2; emits per-node max/min
//    over K and per-channel sum/sumsq (BN2 stats). Block: 8 nodes x 16 edges
//    = 128 edge-rows x 128 out-cols, K=128.
// ---------------------------------------------------------------------------
__global__ __launch_bounds__(256) void k_edge(const float* __restrict__ sW2, const float* __restrict__ sb2,
                                              const float* __restrict__ tW2, const float* __restrict__ tb2) {
    __shared__ float Zs[32][LDW];
    __shared__ float Ws[32][LDW];
    __shared__ int   sidx[128];
    __shared__ float s_sum[HDIM], s_sq[HDIM];
    const int st = blockIdx.z;
    const float* W2 = st ? tW2 : sW2;
    const float* B2 = st ? tb2 : sb2;
    const float* P  = g_p[st];
    const float* Q  = g_q[st];
    const float* A1 = g_a1[st];
    const float* C1 = g_c1[st];
    const int node0 = blockIdx.x * 8;
    const int tid = threadIdx.x, ty = tid >> 4, tx = tid & 15;
    if (tid < 128) {
        sidx[tid]  = g_idx[(size_t)node0 * KNEIGH + tid];
        s_sum[tid] = 0.f;
        s_sq[tid]  = 0.f;
    }
    ull acc[8][4];
#pragma unroll
    for (int i = 0; i < 8; i++)
#pragma unroll
        for (int j = 0; j < 4; j++) acc[i][j] = 0ull;

    for (int kc = 0; kc < HDIM; kc += 32) {
        __syncthreads();
        for (int idx = tid; idx < 128 * 32; idx += 256) {
            int e = idx >> 5, kk = idx & 31;
            int ch = kc + kk;
            int n = node0 + (e >> 4);
            int j = sidx[e];
            float hv = P[(size_t)n * HDIM + ch] + Q[(size_t)j * HDIM + ch];
            Zs[kk][e] = fmaxf(fmaf(A1[ch], hv, C1[ch]), 0.f);
        }
        for (int idx = tid; idx < 32 * HDIM; idx += 256) {
            int kk = idx >> 7, col = idx & 127;
            Ws[kk][col] = W2[(size_t)(kc + kk) * HDIM + col];
        }
        __syncthreads();
#pragma unroll 8
        for (int kk = 0; kk < 32; kk++)
            micro_step(&Zs[kk][0], &Ws[kk][0], ty * 8, tx * 8, acc);
    }
    float outv[8][8];
    unpack_acc(acc, outv);
    float bj[8];
#pragma unroll
    for (int j = 0; j < 8; j++) bj[j] = B2[tx * 8 + j];
#pragma unroll
    for (int j = 0; j < 8; j++) {
        float cs = 0.f, cq = 0.f, cmx = -3.0e38f, cmn = 3.0e38f;
#pragma unroll
        for (int i = 0; i < 8; i++) {
            float v = outv[i][j] + bj[j];
            cs += v; cq += v * v;
            cmx = fmaxf(cmx, v); cmn = fminf(cmn, v);
        }
        // combine the two ty-halves of each 16-edge node group (lanes 16 apart)
        cs  += __shfl_xor_sync(0xffffffffu, cs, 16);
        cq  += __shfl_xor_sync(0xffffffffu, cq, 16);
        cmx  = fmaxf(cmx, __shfl_xor_sync(0xffffffffu, cmx, 16));
        cmn  = fminf(cmn, __shfl_xor_sync(0xffffffffu, cmn, 16));
        if ((ty & 1) == 0) {
            int node = node0 + (ty >> 1);
            int col  = tx * 8 + j;
            g_aggmax[st][(size_t)node * HDIM + col] = cmx;
            g_aggmin[st][(size_t)node * HDIM + col] = cmn;
            atomicAdd(&s_sum[col], cs);
            atomicAdd(&s_sq[col], cq);
        }
    }
    __syncthreads();
    if (tid < HDIM) {
        atomicAdd(&g_bn2_sum[st][tid], s_sum[tid]);
        atomicAdd(&g_bn2_sq[st][tid], s_sq[tid]);
    }
}

// ---------------------------------------------------------------------------
// 8: final GEMM: comb (NTx256, built on the fly from aggregates) @ f_W + f_b
//    writes hF and accumulates BN-F stats.
// ---------------------------------------------------------------------------
__global__ __launch_bounds__(256) void k_final(const float* __restrict__ fW, const float* __restrict__ fb) {
    __shared__ float Fs[32][LDW];
    __shared__ float Ws[32][LDW];
    __shared__ float s_sum[HDIM], s_sq[HDIM];
    const int n0 = blockIdx.x * 128;
    const int tid = threadIdx.x, ty = tid >> 4, tx = tid & 15;
    if (tid < 128) { s_sum[tid] = 0.f; s_sq[tid] = 0.f; }
    ull acc[8][4];
#pragma unroll
    for (int i = 0; i < 8; i++)
#pragma unroll
        for (int j = 0; j < 4; j++) acc[i][j] = 0ull;

    for (int kc = 0; kc < 2 * HDIM; kc += 32) {
        __syncthreads();
        for (int idx = tid; idx < 128 * 32; idx += 256) {
            int nl = idx >> 5, kk = idx & 31;
            int kf = kc + kk;
            int st = kf >> 7, ch = kf & 127;
            float a2 = g_a2[st][ch], c2 = g_c2[st][ch];
            size_t o = (size_t)(n0 + nl) * HDIM + ch;
            float v = (a2 >= 0.f) ? g_aggmax[st][o] : g_aggmin[st][o];
            Fs[kk][nl] = fmaxf(fmaf(a2, v, c2), 0.f);
        }
        for (int idx = tid; idx < 32 * HDIM; idx += 256) {
            int kk = idx >> 7, col = idx & 127;
            Ws[kk][col] = fW[(size_t)(kc + kk) * HDIM + col];
        }
        __syncthreads();
#pragma unroll 8
        for (int kk = 0; kk < 32; kk++)
            micro_step(&Fs[kk][0], &Ws[kk][0], ty * 8, tx * 8, acc);
    }
    float outv[8][8];
    unpack_acc(acc, outv);
    float bj[8];
#pragma unroll
    for (int j = 0; j < 8; j++) bj[j] = fb[tx * 8 + j];
#pragma unroll
    for (int i = 0; i < 8; i++)
#pragma unroll
        for (int j = 0; j < 8; j++) outv[i][j] += bj[j];
#pragma unroll
    for (int i = 0; i < 8; i++) {
        size_t row = (size_t)(n0 + ty * 8 + i) * HDIM + tx * 8;
        *(float4*)&g_hF[row]     = make_float4(outv[i][0], outv[i][1], outv[i][2], outv[i][3]);
        *(float4*)&g_hF[row + 4] = make_float4(outv[i][4], outv[i][5], outv[i][6], outv[i][7]);
    }
#pragma unroll
    for (int j = 0; j < 8; j++) {
        float cs = 0.f, cq = 0.f;
#pragma unroll
        for (int i = 0; i < 8; i++) { float v = outv[i][j]; cs += v; cq += v * v; }
        cs += __shfl_xor_sync(0xffffffffu, cs, 16);
        cq += __shfl_xor_sync(0xffffffffu, cq, 16);
        if ((ty & 1) == 0) {
            int col = tx * 8 + j;
            atomicAdd(&s_sum[col], cs);
            atomicAdd(&s_sq[col], cq);
        }
    }
    __syncthreads();
    if (tid < HDIM) {
        atomicAdd(&g_bnF_sum[tid], s_sum[tid]);
        atomicAdd(&g_bnF_sq[tid], s_sq[tid]);
    }
}

// ---------------------------------------------------------------------------
// 9: output elementwise: relu(aF*hF + cF)
// ---------------------------------------------------------------------------
__global__ void k_out(float* __restrict__ out) {
    int idx = blockIdx.x * 256 + threadIdx.x;
    int col = idx & 127;
    out[idx] = fmaxf(fmaf(g_aF[col], g_hF[idx], g_cF[col]), 0.f);
}

// ---------------------------------------------------------------------------
// launcher
// ---------------------------------------------------------------------------
extern "C" void kernel_launch(void* const* d_in, const int* in_sizes, int n_in,
                              void* d_out, int out_size) {
    (void)in_sizes; (void)n_in; (void)out_size;
    const float* x     = (const float*)d_in[0];
    // d_in[1] = batch (unused: sorted, equal-size graphs)
    const float* s_W1  = (const float*)d_in[2];
    const float* s_b1  = (const float*)d_in[3];
    const float* s_g1  = (const float*)d_in[4];
    const float* s_be1 = (const float*)d_in[5];
    const float* s_W2  = (const float*)d_in[6];
    const float* s_b2  = (const float*)d_in[7];
    const float* s_g2  = (const float*)d_in[8];
    const float* s_be2 = (const float*)d_in[9];
    const float* t_W1  = (const float*)d_in[10];
    const float* t_b1  = (const float*)d_in[11];
    const float* t_g1  = (const float*)d_in[12];
    const float* t_be1 = (const float*)d_in[13];
    const float* t_W2  = (const float*)d_in[14];
    const float* t_b2  = (const float*)d_in[15];
    const float* t_g2  = (const float*)d_in[16];
    const float* t_be2 = (const float*)d_in[17];
    const float* f_W   = (const float*)d_in[18];
    const float* f_b   = (const float*)d_in[19];
    const float* f_g   = (const float*)d_in[20];
    const float* f_be  = (const float*)d_in[21];
    float* out = (float*)d_out;

    const float invE  = 1.f / (float)EDGES;
    const float invNT = 1.f / (float)NT;

    k_zero<<<1, 128>>>();
    k_sq<<<NT / 8, 256>>>(x);
    k_d2<<<dim3(NNODE / 128, NNODE / 128, BBATCH), 256>>>(x);
    k_topk<<<NT, 256>>>();
    k_pq<<<dim3(NT / 128, 1, 4), 256>>>(x, s_W1, s_b1, t_W1, t_b1);
    k_bn1stats<<<NT / 32, 128>>>();
    k_bnfin<<<1, 128>>>(0, 0, s_g1, s_be1, invE);
    k_bnfin<<<1, 128>>>(0, 1, t_g1, t_be1, invE);
    k_edge<<<dim3(NT / 8, 1, 2), 256>>>(s_W2, s_b2, t_W2, t_b2);
    k_bnfin<<<1, 128>>>(1, 0, s_g2, s_be2, invE);
    k_bnfin<<<1, 128>>>(1, 1, t_g2, t_be2, invE);
    k_final<<<NT / 128, 256>>>(f_W, f_b);
    k_bnfin<<<1, 128>>>(2, 0, f_g, f_be, invNT);
    k_out<<<(NT * HDIM) / 256, 256>>>(out);
}

// round 6
// speedup vs baseline: 1.3175x; 1.3175x over previous
#include <cuda_runtime.h>
#include <cuda_bf16.h>

#define BBATCH 16
#define NNODE  2048
#define CDIM   64
#define HDIM   128
#define KNEIGH 16
#define NT     (BBATCH*NNODE)        /* 32768 nodes  */
#define EDGES  (NT*KNEIGH)           /* 524288 edges */
#define BN_EPS 1e-5f
#define LDW    132                   /* smem tile pitch (floats): 16B-aligned, 4-way max conflicts */
#define TKW    4                     /* top-k: rows (warps) per block */

typedef unsigned long long ull;

// ---------------------------------------------------------------------------
// Static device scratch (no runtime allocation allowed)
// ---------------------------------------------------------------------------
__device__ float g_sq[NT];
__device__ float g_d2[(size_t)BBATCH * NNODE * NNODE];        // 256 MB
__device__ int   g_idx[EDGES];                                 // global neighbor idx
__device__ float g_p[2][(size_t)NT * HDIM];
__device__ float g_q[2][(size_t)NT * HDIM];
__device__ float g_bn1_sum[2][HDIM], g_bn1_sq[2][HDIM];
__device__ float g_a1[2][HDIM], g_c1[2][HDIM];
__device__ float g_aggmax[2][(size_t)NT * HDIM];
__device__ float g_aggmin[2][(size_t)NT * HDIM];
__device__ float g_bn2_sum[2][HDIM], g_bn2_sq[2][HDIM];
__device__ float g_a2[2][HDIM], g_c2[2][HDIM];
__device__ float g_hF[(size_t)NT * HDIM];
__device__ float g_bnF_sum[HDIM], g_bnF_sq[HDIM];
__device__ float g_aF[HDIM], g_cF[HDIM];

// ---------------------------------------------------------------------------
// f32x2 packed-FMA helpers (sm_100+ PTX; FFMA2 is PTX-only per SASS quickref)
// ---------------------------------------------------------------------------
__device__ __forceinline__ ull pk2(float lo, float hi) {
    ull r; asm("mov.b64 %0, {%1, %2};" : "=l"(r) : "f"(lo), "f"(hi)); return r;
}
__device__ __forceinline__ void fma2(ull &d, ull a, ull b) {
    asm("fma.rn.f32x2 %0, %1, %2, %0;" : "+l"(d) : "l"(a), "l"(b));
}
__device__ __forceinline__ float2 up2(ull v) {
    float2 f; asm("mov.b64 {%0, %1}, %2;" : "=f"(f.x), "=f"(f.y) : "l"(v)); return f;
}

// 8x8 micro-tile step: A k-major [kk][row], B k-major [kk][col], acc packed pairs along cols
__device__ __forceinline__ void micro_step(const float* __restrict__ Arow,
                                           const float* __restrict__ Brow,
                                           int ty8, int tx8, ull acc[8][4]) {
    float4 a0 = *(const float4*)(Arow + ty8);
    float4 a1 = *(const float4*)(Arow + ty8 + 4);
    float4 b0 = *(const float4*)(Brow + tx8);
    float4 b1 = *(const float4*)(Brow + tx8 + 4);
    ull bv0 = pk2(b0.x, b0.y), bv1 = pk2(b0.z, b0.w);
    ull bv2 = pk2(b1.x, b1.y), bv3 = pk2(b1.z, b1.w);
    float av[8] = {a0.x, a0.y, a0.z, a0.w, a1.x, a1.y, a1.z, a1.w};
#pragma unroll
    for (int i = 0; i < 8; i++) {
        ull ai = pk2(av[i], av[i]);
        fma2(acc[i][0], ai, bv0);
        fma2(acc[i][1], ai, bv1);
        fma2(acc[i][2], ai, bv2);
        fma2(acc[i][3], ai, bv3);
    }
}

__device__ __forceinline__ void unpack_acc(ull acc[8][4], float outv[8][8]) {
#pragma unroll
    for (int i = 0; i < 8; i++)
#pragma unroll
        for (int j2 = 0; j2 < 4; j2++) {
            float2 u = up2(acc[i][j2]);
            outv[i][2*j2]   = u.x;
            outv[i][2*j2+1] = u.y;
        }
}

// ---------------------------------------------------------------------------
// 0: zero accumulators (must run every launch: graph replays reuse globals)
// ---------------------------------------------------------------------------
__global__ void k_zero() {
    int t = threadIdx.x;
    if (t < HDIM) {
        g_bn1_sum[0][t] = 0.f; g_bn1_sum[1][t] = 0.f;
        g_bn1_sq[0][t]  = 0.f; g_bn1_sq[1][t]  = 0.f;
        g_bn2_sum[0][t] = 0.f; g_bn2_sum[1][t] = 0.f;
        g_bn2_sq[0][t]  = 0.f; g_bn2_sq[1][t]  = 0.f;
        g_bnF_sum[t]    = 0.f; g_bnF_sq[t]     = 0.f;
    }
}

// ---------------------------------------------------------------------------
// 1: per-node squared norms (one warp per node)
// ---------------------------------------------------------------------------
__global__ void k_sq(const float* __restrict__ x) {
    int w    = (blockIdx.x * blockDim.x + threadIdx.x) >> 5;
    int lane = threadIdx.x & 31;
    if (w >= NT) return;
    float v0 = x[(size_t)w * CDIM + lane];
    float v1 = x[(size_t)w * CDIM + 32 + lane];
    float s = v0 * v0 + v1 * v1;
#pragma unroll
    for (int off = 16; off; off >>= 1) s += __shfl_xor_sync(0xffffffffu, s, off);
    if (lane == 0) g_sq[w] = s;
}

// ---------------------------------------------------------------------------
// 2: pairwise squared distances per batch (128x128x64 tiles)
// ---------------------------------------------------------------------------
__global__ __launch_bounds__(256) void k_d2(const float* __restrict__ x) {
    __shared__ float Ai[32][LDW];
    __shared__ float Aj[32][LDW];
    const int b  = blockIdx.z;
    const int i0 = blockIdx.y * 128, j0 = blockIdx.x * 128;
    const float* X = x + (size_t)b * NNODE * CDIM;
    const int tid = threadIdx.x, ty = tid >> 4, tx = tid & 15;
    ull acc[8][4];
#pragma unroll
    for (int i = 0; i < 8; i++)
#pragma unroll
        for (int j = 0; j < 4; j++) acc[i][j] = 0ull;

    for (int kc = 0; kc < CDIM; kc += 32) {
        __syncthreads();
        for (int idx = tid; idx < 128 * 32; idx += 256) {
            int row = idx >> 5, kk = idx & 31;
            Ai[kk][row] = X[(size_t)(i0 + row) * CDIM + kc + kk];
            Aj[kk][row] = X[(size_t)(j0 + row) * CDIM + kc + kk];
        }
        __syncthreads();
#pragma unroll 8
        for (int kk = 0; kk < 32; kk++)
            micro_step(&Ai[kk][0], &Aj[kk][0], ty * 8, tx * 8, acc);
    }
    float outv[8][8];
    unpack_acc(acc, outv);
    float sqi[8], sqj[8];
#pragma unroll
    for (int i = 0; i < 8; i++) sqi[i] = g_sq[b * NNODE + i0 + ty * 8 + i];
#pragma unroll
    for (int j = 0; j < 8; j++) sqj[j] = g_sq[b * NNODE + j0 + tx * 8 + j];
#pragma unroll
    for (int i = 0; i < 8; i++) {
        size_t row = ((size_t)(b * NNODE + i0 + ty * 8 + i)) * NNODE + j0 + tx * 8;
        float v[8];
#pragma unroll
        for (int j = 0; j < 8; j++) v[j] = sqi[i] + sqj[j] - 2.f * outv[i][j];
        *(float4*)&g_d2[row]     = make_float4(v[0], v[1], v[2], v[3]);
        *(float4*)&g_d2[row + 4] = make_float4(v[4], v[5], v[6], v[7]);
    }
}

// ---------------------------------------------------------------------------
// 3: top-K smallest per row. One WARP per row: 32 lanes x 64 values in smem.
//    Per-lane cached (min, argmin); each round = warp argmin + winner rescan.
//    No block syncs, no smem atomics.
// ---------------------------------------------------------------------------
__global__ __launch_bounds__(32 * TKW) void k_topk() {
    __shared__ float vals[TKW][NNODE];     // 32 KB
    const int warp = threadIdx.x >> 5, lane = threadIdx.x & 31;
    const int row  = blockIdx.x * TKW + warp;
    const size_t rowoff = (size_t)row * NNODE;
    const int b = row >> 11;               // NNODE = 2048
    float* v = vals[warp];

    // coalesced row load (each warp loads its own row)
    for (int j = lane; j < NNODE; j += 32) v[j] = g_d2[rowoff + j];
    __syncwarp();

    // per-lane (min, argmin) over its 64 strided values
    float bm = 3.0e38f; int bi = 0x7fffffff;
#pragma unroll 16
    for (int j = lane; j < NNODE; j += 32) {
        float x = v[j];
        if (x < bm) { bm = x; bi = j; }
    }

    for (int k = 0; k < KNEIGH; k++) {
        // warp argmin (value, then smaller index) -> all lanes get result
        float wv = bm; int wi = bi;
#pragma unroll
        for (int off = 16; off; off >>= 1) {
            float ov = __shfl_xor_sync(0xffffffffu, wv, off);
            int   oi = __shfl_xor_sync(0xffffffffu, wi, off);
            if (ov < wv || (ov == wv && oi < wi)) { wv = ov; wi = oi; }
        }
        if (lane == 0) g_idx[(size_t)row * KNEIGH + k] = b * NNODE + wi;
        // winning lane removes the element and rescans its 64 values
        if ((wi & 31) == lane) {
            v[wi] = 3.0e38f;
            bm = 3.0e38f; bi = 0x7fffffff;
#pragma unroll 16
            for (int j = lane; j < NNODE; j += 32) {
                float x = v[j];
                if (x < bm) { bm = x; bi = j; }
            }
        }
        __syncwarp();
    }
}

// ---------------------------------------------------------------------------
// 4: p/q GEMMs. z: 0=s/p, 1=s/q, 2=t/p, 3=t/q
// ---------------------------------------------------------------------------
__global__ __launch_bounds__(256) void k_pq(const float* __restrict__ x,
                                            const float* __restrict__ sW1, const float* __restrict__ sb1,
                                            const float* __restrict__ tW1, const float* __restrict__ tb1) {
    __shared__ float Xs[32][LDW];
    __shared__ float Ws[32][LDW];
    const int z   = blockIdx.z;
    const int st  = z >> 1;
    const bool isP = (z & 1) == 0;
    const float* W1 = st ? tW1 : sW1;
    const float* B1 = st ? tb1 : sb1;
    const int n0 = blockIdx.x * 128;
    const int tid = threadIdx.x, ty = tid >> 4, tx = tid & 15;
    ull acc[8][4];
#pragma unroll
    for (int i = 0; i < 8; i++)
#pragma unroll
        for (int j = 0; j < 4; j++) acc[i][j] = 0ull;

    for (int kc = 0; kc < CDIM; kc += 32) {
        __syncthreads();
        for (int idx = tid; idx < 128 * 32; idx += 256) {
            int r = idx >> 5, kk = idx & 31;
            Xs[kk][r] = x[(size_t)(n0 + r) * CDIM + kc + kk];
        }
        for (int idx = tid; idx < 32 * HDIM; idx += 256) {
            int kk = idx >> 7, col = idx & 127;
            int kr = kc + kk;
            float w = W1[(size_t)(CDIM + kr) * HDIM + col];
            if (isP) w = W1[(size_t)kr * HDIM + col] - w;
            Ws[kk][col] = w;
        }
        __syncthreads();
#pragma unroll 8
        for (int kk = 0; kk < 32; kk++)
            micro_step(&Xs[kk][0], &Ws[kk][0], ty * 8, tx * 8, acc);
    }
    float outv[8][8];
    unpack_acc(acc, outv);
    float* O = isP ? g_p[st] : g_q[st];
    float bj[8];
#pragma unroll
    for (int j = 0; j < 8; j++) bj[j] = isP ? B1[tx * 8 + j] : 0.f;
#pragma unroll
    for (int i = 0; i < 8; i++) {
        size_t row = (size_t)(n0 + ty * 8 + i) * HDIM + tx * 8;
        *(float4*)&O[row]     = make_float4(outv[i][0] + bj[0], outv[i][1] + bj[1],
                                            outv[i][2] + bj[2], outv[i][3] + bj[3]);
        *(float4*)&O[row + 4] = make_float4(outv[i][4] + bj[4], outv[i][5] + bj[5],
                                            outv[i][6] + bj[6], outv[i][7] + bj[7]);
    }
}

// ---------------------------------------------------------------------------
// 5: BN1 statistics over all edges, both streams (h1 = p[n] + q[j])
// ---------------------------------------------------------------------------
__global__ void k_bn1stats() {
    const int h = threadIdx.x;          // 128 threads = channels
    const int node0 = blockIdx.x * 32;  // 1024 blocks x 32 nodes
    float s0 = 0.f, q0 = 0.f, s1 = 0.f, q1 = 0.f;
    for (int nl = 0; nl < 32; nl++) {
        int n = node0 + nl;
        float p0 = g_p[0][(size_t)n * HDIM + h];
        float p1 = g_p[1][(size_t)n * HDIM + h];
        for (int k = 0; k < KNEIGH; k++) {
            int j = g_idx[(size_t)n * KNEIGH + k];
            float a = p0 + g_q[0][(size_t)j * HDIM + h];
            float b = p1 + g_q[1][(size_t)j * HDIM + h];
            s0 += a; q0 += a * a;
            s1 += b; q1 += b * b;
        }
    }
    atomicAdd(&g_bn1_sum[0][h], s0); atomicAdd(&g_bn1_sq[0][h], q0);
    atomicAdd(&g_bn1_sum[1][h], s1); atomicAdd(&g_bn1_sq[1][h], q1);
}

// ---------------------------------------------------------------------------
// 6: BN finalize -> per-channel affine (a, c). which: 0=bn1, 1=bn2, 2=bnF
// ---------------------------------------------------------------------------
__global__ void k_bnfin(int which, int st, const float* __restrict__ g,
                        const float* __restrict__ be, float invN) {
    int h = threadIdx.x;
    float s, q;
    if (which == 0)      { s = g_bn1_sum[st][h]; q = g_bn1_sq[st][h]; }
    else if (which == 1) { s = g_bn2_sum[st][h]; q = g_bn2_sq[st][h]; }
    else                 { s = g_bnF_sum[h];     q = g_bnF_sq[h]; }
    float m   = s * invN;
    float var = fmaxf(q * invN - m * m, 0.f);
    float a   = g[h] * rsqrtf(var + BN_EPS);
    float c   = be[h] - m * a;
    if (which == 0)      { g_a1[st][h] = a; g_c1[st][h] = c; }
    else if (which == 1) { g_a2[st][h] = a; g_c2[st][h] = c; }
    else                 { g_aF[h] = a;     g_cF[h] = c; }
}

// ---------------------------------------------------------------------------
// 7: edge GEMM: z = relu(bn1(h1)), h2 = z @ W2 + b2; emits per-node max/min
//    over K and per-channel sum/sumsq (BN2 stats). Block: 8 nodes x 16 edges
//    = 128 edge-rows x 128 out-cols, K=128.
// ---------------------------------------------------------------------------
__global__ __launch_bounds__(256) void k_edge(const float* __restrict__ sW2, const float* __restrict__ sb2,
                                              const float* __restrict__ tW2, const float* __restrict__ tb2) {
    __shared__ float Zs[32][LDW];
    __shared__ float Ws[32][LDW];
    __shared__ int   sidx[128];
    __shared__ float s_sum[HDIM], s_sq[HDIM];
    const int st = blockIdx.z;
    const float* W2 = st ? tW2 : sW2;
    const float* B2 = st ? tb2 : sb2;
    const float* P  = g_p[st];
    const float* Q  = g_q[st];
    const float* A1 = g_a1[st];
    const float* C1 = g_c1[st];
    const int node0 = blockIdx.x * 8;
    const int tid = threadIdx.x, ty = tid >> 4, tx = tid & 15;
    if (tid < 128) {
        sidx[tid]  = g_idx[(size_t)node0 * KNEIGH + tid];
        s_sum[tid] = 0.f;
        s_sq[tid]  = 0.f;
    }
    ull acc[8][4];
#pragma unroll
    for (int i = 0; i < 8; i++)
#pragma unroll
        for (int j = 0; j < 4; j++) acc[i][j] = 0ull;

    for (int kc = 0; kc < HDIM; kc += 32) {
        __syncthreads();
        for (int idx = tid; idx < 128 * 32; idx += 256) {
            int e = idx >> 5, kk = idx & 31;
            int ch = kc + kk;
            int n = node0 + (e >> 4);
            int j = sidx[e];
            float hv = P[(size_t)n * HDIM + ch] + Q[(size_t)j * HDIM + ch];
            Zs[kk][e] = fmaxf(fmaf(A1[ch], hv, C1[ch]), 0.f);
        }
        for (int idx = tid; idx < 32 * HDIM; idx += 256) {
            int kk = idx >> 7, col = idx & 127;
            Ws[kk][col] = W2[(size_t)(kc + kk) * HDIM + col];
        }
        __syncthreads();
#pragma unroll 8
        for (int kk = 0; kk < 32; kk++)
            micro_step(&Zs[kk][0], &Ws[kk][0], ty * 8, tx * 8, acc);
    }
    float outv[8][8];
    unpack_acc(acc, outv);
    float bj[8];
#pragma unroll
    for (int j = 0; j < 8; j++) bj[j] = B2[tx * 8 + j];
#pragma unroll
    for (int j = 0; j < 8; j++) {
        float cs = 0.f, cq = 0.f, cmx = -3.0e38f, cmn = 3.0e38f;
#pragma unroll
        for (int i = 0; i < 8; i++) {
            float v = outv[i][j] + bj[j];
            cs += v; cq += v * v;
            cmx = fmaxf(cmx, v); cmn = fminf(cmn, v);
        }
        // combine the two ty-halves of each 16-edge node group (lanes 16 apart)
        cs  += __shfl_xor_sync(0xffffffffu, cs, 16);
        cq  += __shfl_xor_sync(0xffffffffu, cq, 16);
        cmx  = fmaxf(cmx, __shfl_xor_sync(0xffffffffu, cmx, 16));
        cmn  = fminf(cmn, __shfl_xor_sync(0xffffffffu, cmn, 16));
        if ((ty & 1) == 0) {
            int node = node0 + (ty >> 1);
            int col  = tx * 8 + j;
            g_aggmax[st][(size_t)node * HDIM + col] = cmx;
            g_aggmin[st][(size_t)node * HDIM + col] = cmn;
            atomicAdd(&s_sum[col], cs);
            atomicAdd(&s_sq[col], cq);
        }
    }
    __syncthreads();
    if (tid < HDIM) {
        atomicAdd(&g_bn2_sum[st][tid], s_sum[tid]);
        atomicAdd(&g_bn2_sq[st][tid], s_sq[tid]);
    }
}

// ---------------------------------------------------------------------------
// 8: final GEMM: comb (NTx256, built on the fly from aggregates) @ f_W + f_b
//    writes hF and accumulates BN-F stats.
// ---------------------------------------------------------------------------
__global__ __launch_bounds__(256) void k_final(const float* __restrict__ fW, const float* __restrict__ fb) {
    __shared__ float Fs[32][LDW];
    __shared__ float Ws[32][LDW];
    __shared__ float s_sum[HDIM], s_sq[HDIM];
    const int n0 = blockIdx.x * 128;
    const int tid = threadIdx.x, ty = tid >> 4, tx = tid & 15;
    if (tid < 128) { s_sum[tid] = 0.f; s_sq[tid] = 0.f; }
    ull acc[8][4];
#pragma unroll
    for (int i = 0; i < 8; i++)
#pragma unroll
        for (int j = 0; j < 4; j++) acc[i][j] = 0ull;

    for (int kc = 0; kc < 2 * HDIM; kc += 32) {
        __syncthreads();
        for (int idx = tid; idx < 128 * 32; idx += 256) {
            int nl = idx >> 5, kk = idx & 31;
            int kf = kc + kk;
            int st = kf >> 7, ch = kf & 127;
            float a2 = g_a2[st][ch], c2 = g_c2[st][ch];
            size_t o = (size_t)(n0 + nl) * HDIM + ch;
            float v = (a2 >= 0.f) ? g_aggmax[st][o] : g_aggmin[st][o];
            Fs[kk][nl] = fmaxf(fmaf(a2, v, c2), 0.f);
        }
        for (int idx = tid; idx < 32 * HDIM; idx += 256) {
            int kk = idx >> 7, col = idx & 127;
            Ws[kk][col] = fW[(size_t)(kc + kk) * HDIM + col];
        }
        __syncthreads();
#pragma unroll 8
        for (int kk = 0; kk < 32; kk++)
            micro_step(&Fs[kk][0], &Ws[kk][0], ty * 8, tx * 8, acc);
    }
    float outv[8][8];
    unpack_acc(acc, outv);
    float bj[8];
#pragma unroll
    for (int j = 0; j < 8; j++) bj[j] = fb[tx * 8 + j];
#pragma unroll
    for (int i = 0; i < 8; i++)
#pragma unroll
        for (int j = 0; j < 8; j++) outv[i][j] += bj[j];
#pragma unroll
    for (int i = 0; i < 8; i++) {
        size_t row = (size_t)(n0 + ty * 8 + i) * HDIM + tx * 8;
        *(float4*)&g_hF[row]     = make_float4(outv[i][0], outv[i][1], outv[i][2], outv[i][3]);
        *(float4*)&g_hF[row + 4] = make_float4(outv[i][4], outv[i][5], outv[i][6], outv[i][7]);
    }
#pragma unroll
    for (int j = 0; j < 8; j++) {
        float cs = 0.f, cq = 0.f;
#pragma unroll
        for (int i = 0; i < 8; i++) { float v = outv[i][j]; cs += v; cq += v * v; }
        cs += __shfl_xor_sync(0xffffffffu, cs, 16);
        cq += __shfl_xor_sync(0xffffffffu, cq, 16);
        if ((ty & 1) == 0) {
            int col = tx * 8 + j;
            atomicAdd(&s_sum[col], cs);
            atomicAdd(&s_sq[col], cq);
        }
    }
    __syncthreads();
    if (tid < HDIM) {
        atomicAdd(&g_bnF_sum[tid], s_sum[tid]);
        atomicAdd(&g_bnF_sq[tid], s_sq[tid]);
    }
}

// ---------------------------------------------------------------------------
// 9: output elementwise: relu(aF*hF + cF)
// ---------------------------------------------------------------------------
__global__ void k_out(float* __restrict__ out) {
    int idx = blockIdx.x * 256 + threadIdx.x;
    int col = idx & 127;
    out[idx] = fmaxf(fmaf(g_aF[col], g_hF[idx], g_cF[col]), 0.f);
}

// ---------------------------------------------------------------------------
// launcher
// ---------------------------------------------------------------------------
extern "C" void kernel_launch(void* const* d_in, const int* in_sizes, int n_in,
                              void* d_out, int out_size) {
    (void)in_sizes; (void)n_in; (void)out_size;
    const float* x     = (const float*)d_in[0];
    // d_in[1] = batch (unused: sorted, equal-size graphs)
    const float* s_W1  = (const float*)d_in[2];
    const float* s_b1  = (const float*)d_in[3];
    const float* s_g1  = (const float*)d_in[4];
    const float* s_be1 = (const float*)d_in[5];
    const float* s_W2  = (const float*)d_in[6];
    const float* s_b2  = (const float*)d_in[7];
    const float* s_g2  = (const float*)d_in[8];
    const float* s_be2 = (const float*)d_in[9];
    const float* t_W1  = (const float*)d_in[10];
    const float* t_b1  = (const float*)d_in[11];
    const float* t_g1  = (const float*)d_in[12];
    const float* t_be1 = (const float*)d_in[13];
    const float* t_W2  = (const float*)d_in[14];
    const float* t_b2  = (const float*)d_in[15];
    const float* t_g2  = (const float*)d_in[16];
    const float* t_be2 = (const float*)d_in[17];
    const float* f_W   = (const float*)d_in[18];
    const float* f_b   = (const float*)d_in[19];
    const float* f_g   = (const float*)d_in[20];
    const float* f_be  = (const float*)d_in[21];
    float* out = (float*)d_out;

    const float invE  = 1.f / (float)EDGES;
    const float invNT = 1.f / (float)NT;

    k_zero<<<1, 128>>>();
    k_sq<<<NT / 8, 256>>>(x);
    k_d2<<<dim3(NNODE / 128, NNODE / 128, BBATCH), 256>>>(x);
    k_topk<<<NT / TKW, 32 * TKW>>>();
    k_pq<<<dim3(NT / 128, 1, 4), 256>>>(x, s_W1, s_b1, t_W1, t_b1);
    k_bn1stats<<<NT / 32, 128>>>();
    k_bnfin<<<1, 128>>>(0, 0, s_g1, s_be1, invE);
    k_bnfin<<<1, 128>>>(0, 1, t_g1, t_be1, invE);
    k_edge<<<dim3(NT / 8, 1, 2), 256>>>(s_W2, s_b2, t_W2, t_b2);
    k_bnfin<<<1, 128>>>(1, 0, s_g2, s_be2, invE);
    k_bnfin<<<1, 128>>>(1, 1, t_g2, t_be2, invE);
    k_final<<<NT / 128, 256>>>(f_W, f_b);
    k_bnfin<<<1, 128>>>(2, 0, f_g, f_be, invNT);
    k_out<<<(NT * HDIM) / 256, 256>>>(out);
}

// round 11
// speedup vs baseline: 1.5341x; 1.1643x over previous
#include <cuda_runtime.h>
#include <cuda_bf16.h>
#include <cstdint>

#define BBATCH 16
#define NNODE  2048
#define CDIM   64
#define HDIM   128
#define KNEIGH 16
#define NT     (BBATCH*NNODE)        /* 32768 nodes  */
#define EDGES  (NT*KNEIGH)           /* 524288 edges */
#define BN_EPS 1e-5f
#define LDW    132                   /* smem tile pitch (floats) for FFMA GEMMs */
#define TKW    4                     /* top-k: rows (warps) per block */
#define BKP    136                   /* bf16 tile pitch (elements) for mma tiles */
#define W2T_BYTES (HDIM*BKP*2)       /* 34816 bytes per hi/lo tile */
#define EDGE_SMEM (4*W2T_BYTES)      /* 139264 */

typedef unsigned long long ull;

// ---------------------------------------------------------------------------
// Static device scratch (no runtime allocation allowed)
// ---------------------------------------------------------------------------
__device__ float g_sq[NT];
__device__ float g_d2[(size_t)BBATCH * NNODE * NNODE];        // 256 MB
__device__ int   g_idx[EDGES];
__device__ __align__(16) float g_p[2][(size_t)NT * HDIM];
__device__ __align__(16) float g_q[2][(size_t)NT * HDIM];
__device__ float g_bn1_sum[2][HDIM], g_bn1_sq[2][HDIM];
__device__ __align__(16) float g_a1[2][HDIM], g_c1[2][HDIM];
__device__ __align__(16) float g_aggmax[2][(size_t)NT * HDIM];
__device__ __align__(16) float g_aggmin[2][(size_t)NT * HDIM];
__device__ float g_bn2_sum[2][HDIM], g_bn2_sq[2][HDIM];
__device__ float g_a2[2][HDIM], g_c2[2][HDIM];
__device__ __align__(16) float g_hF[(size_t)NT * HDIM];
__device__ float g_bnF_sum[HDIM], g_bnF_sq[HDIM];
__device__ float g_aF[HDIM], g_cF[HDIM];
// W2^T split into bf16 hi/lo, row-major [n][k] with pitch BKP (raw smem image)
__device__ __align__(16) unsigned char g_w2t_hi[2][W2T_BYTES];
__device__ __align__(16) unsigned char g_w2t_lo[2][W2T_BYTES];

// ---------------------------------------------------------------------------
// f32x2 packed-FMA helpers
// ---------------------------------------------------------------------------
__device__ __forceinline__ ull pk2(float lo, float hi) {
    ull r; asm("mov.b64 %0, {%1, %2};" : "=l"(r) : "f"(lo), "f"(hi)); return r;
}
__device__ __forceinline__ void fma2(ull &d, ull a, ull b) {
    asm("fma.rn.f32x2 %0, %1, %2, %0;" : "+l"(d) : "l"(a), "l"(b));
}
__device__ __forceinline__ float2 up2(ull v) {
    float2 f; asm("mov.b64 {%0, %1}, %2;" : "=f"(f.x), "=f"(f.y) : "l"(v)); return f;
}

__device__ __forceinline__ void micro_step(const float* __restrict__ Arow,
                                           const float* __restrict__ Brow,
                                           int ty8, int tx8, ull acc[8][4]) {
    float4 a0 = *(const float4*)(Arow + ty8);
    float4 a1 = *(const float4*)(Arow + ty8 + 4);
    float4 b0 = *(const float4*)(Brow + tx8);
    float4 b1 = *(const float4*)(Brow + tx8 + 4);
    ull bv0 = pk2(b0.x, b0.y), bv1 = pk2(b0.z, b0.w);
    ull bv2 = pk2(b1.x, b1.y), bv3 = pk2(b1.z, b1.w);
    float av[8] = {a0.x, a0.y, a0.z, a0.w, a1.x, a1.y, a1.z, a1.w};
#pragma unroll
    for (int i = 0; i < 8; i++) {
        ull ai = pk2(av[i], av[i]);
        fma2(acc[i][0], ai, bv0);
        fma2(acc[i][1], ai, bv1);
        fma2(acc[i][2], ai, bv2);
        fma2(acc[i][3], ai, bv3);
    }
}

__device__ __forceinline__ void unpack_acc(ull acc[8][4], float outv[8][8]) {
#pragma unroll
    for (int i = 0; i < 8; i++)
#pragma unroll
        for (int j2 = 0; j2 < 4; j2++) {
            float2 u = up2(acc[i][j2]);
            outv[i][2*j2]   = u.x;
            outv[i][2*j2+1] = u.y;
        }
}

// mma.sync bf16 (sm_80 baseline feature — no "a"-arch requirement)
__device__ __forceinline__ void mma16816(float* d, const uint32_t* a, const uint32_t* b) {
    asm volatile(
        "mma.sync.aligned.m16n8k16.row.col.f32.bf16.bf16.f32 "
        "{%0,%1,%2,%3}, {%4,%5,%6,%7}, {%8,%9}, {%0,%1,%2,%3};"
        : "+f"(d[0]), "+f"(d[1]), "+f"(d[2]), "+f"(d[3])
        : "r"(a[0]), "r"(a[1]), "r"(a[2]), "r"(a[3]), "r"(b[0]), "r"(b[1]));
}

// ---------------------------------------------------------------------------
// 0: zero accumulators
// ---------------------------------------------------------------------------
__global__ void k_zero() {
    int t = threadIdx.x;
    if (t < HDIM) {
        g_bn1_sum[0][t] = 0.f; g_bn1_sum[1][t] = 0.f;
        g_bn1_sq[0][t]  = 0.f; g_bn1_sq[1][t]  = 0.f;
        g_bn2_sum[0][t] = 0.f; g_bn2_sum[1][t] = 0.f;
        g_bn2_sq[0][t]  = 0.f; g_bn2_sq[1][t]  = 0.f;
        g_bnF_sum[t]    = 0.f; g_bnF_sq[t]     = 0.f;
    }
}

// ---------------------------------------------------------------------------
// 1: per-node squared norms
// ---------------------------------------------------------------------------
__global__ void k_sq(const float* __restrict__ x) {
    int w    = (blockIdx.x * blockDim.x + threadIdx.x) >> 5;
    int lane = threadIdx.x & 31;
    if (w >= NT) return;
    float v0 = x[(size_t)w * CDIM + lane];
    float v1 = x[(size_t)w * CDIM + 32 + lane];
    float s = v0 * v0 + v1 * v1;
#pragma unroll
    for (int off = 16; off; off >>= 1) s += __shfl_xor_sync(0xffffffffu, s, off);
    if (lane == 0) g_sq[w] = s;
}

// ---------------------------------------------------------------------------
// 2: pairwise squared distances per batch
// ---------------------------------------------------------------------------
__global__ __launch_bounds__(256) void k_d2(const float* __restrict__ x) {
    __shared__ float Ai[32][LDW];
    __shared__ float Aj[32][LDW];
    const int b  = blockIdx.z;
    const int i0 = blockIdx.y * 128, j0 = blockIdx.x * 128;
    const float* X = x + (size_t)b * NNODE * CDIM;
    const int tid = threadIdx.x, ty = tid >> 4, tx = tid & 15;
    ull acc[8][4];
#pragma unroll
    for (int i = 0; i < 8; i++)
#pragma unroll
        for (int j = 0; j < 4; j++) acc[i][j] = 0ull;

    for (int kc = 0; kc < CDIM; kc += 32) {
        __syncthreads();
        for (int idx = tid; idx < 128 * 32; idx += 256) {
            int row = idx >> 5, kk = idx & 31;
            Ai[kk][row] = X[(size_t)(i0 + row) * CDIM + kc + kk];
            Aj[kk][row] = X[(size_t)(j0 + row) * CDIM + kc + kk];
        }
        __syncthreads();
#pragma unroll 8
        for (int kk = 0; kk < 32; kk++)
            micro_step(&Ai[kk][0], &Aj[kk][0], ty * 8, tx * 8, acc);
    }
    float outv[8][8];
    unpack_acc(acc, outv);
    float sqi[8], sqj[8];
#pragma unroll
    for (int i = 0; i < 8; i++) sqi[i] = g_sq[b * NNODE + i0 + ty * 8 + i];
#pragma unroll
    for (int j = 0; j < 8; j++) sqj[j] = g_sq[b * NNODE + j0 + tx * 8 + j];
#pragma unroll
    for (int i = 0; i < 8; i++) {
        size_t row = ((size_t)(b * NNODE + i0 + ty * 8 + i)) * NNODE + j0 + tx * 8;
        float v[8];
#pragma unroll
        for (int j = 0; j < 8; j++) v[j] = sqi[i] + sqj[j] - 2.f * outv[i][j];
        *(float4*)&g_d2[row]     = make_float4(v[0], v[1], v[2], v[3]);
        *(float4*)&g_d2[row + 4] = make_float4(v[4], v[5], v[6], v[7]);
    }
}

// ---------------------------------------------------------------------------
// 3: top-K smallest per row (warp per row)
// ---------------------------------------------------------------------------
__global__ __launch_bounds__(32 * TKW) void k_topk() {
    __shared__ float vals[TKW][NNODE];
    const int warp = threadIdx.x >> 5, lane = threadIdx.x & 31;
    const int row  = blockIdx.x * TKW + warp;
    const size_t rowoff = (size_t)row * NNODE;
    const int b = row >> 11;
    float* v = vals[warp];

    for (int j = lane; j < NNODE; j += 32) v[j] = g_d2[rowoff + j];
    __syncwarp();

    float bm = 3.0e38f; int bi = 0x7fffffff;
#pragma unroll 16
    for (int j = lane; j < NNODE; j += 32) {
        float x = v[j];
        if (x < bm) { bm = x; bi = j; }
    }

    for (int k = 0; k < KNEIGH; k++) {
        float wv = bm; int wi = bi;
#pragma unroll
        for (int off = 16; off; off >>= 1) {
            float ov = __shfl_xor_sync(0xffffffffu, wv, off);
            int   oi = __shfl_xor_sync(0xffffffffu, wi, off);
            if (ov < wv || (ov == wv && oi < wi)) { wv = ov; wi = oi; }
        }
        if (lane == 0) g_idx[(size_t)row * KNEIGH + k] = b * NNODE + wi;
        if ((wi & 31) == lane) {
            v[wi] = 3.0e38f;
            bm = 3.0e38f; bi = 0x7fffffff;
#pragma unroll 16
            for (int j = lane; j < NNODE; j += 32) {
                float x = v[j];
                if (x < bm) { bm = x; bi = j; }
            }
        }
        __syncwarp();
    }
}

// ---------------------------------------------------------------------------
// 4: p/q GEMMs
// ---------------------------------------------------------------------------
__global__ __launch_bounds__(256) void k_pq(const float* __restrict__ x,
                                            const float* __restrict__ sW1, const float* __restrict__ sb1,
                                            const float* __restrict__ tW1, const float* __restrict__ tb1) {
    __shared__ float Xs[32][LDW];
    __shared__ float Ws[32][LDW];
    const int z   = blockIdx.z;
    const int st  = z >> 1;
    const bool isP = (z & 1) == 0;
    const float* W1 = st ? tW1 : sW1;
    const float* B1 = st ? tb1 : sb1;
    const int n0 = blockIdx.x * 128;
    const int tid = threadIdx.x, ty = tid >> 4, tx = tid & 15;
    ull acc[8][4];
#pragma unroll
    for (int i = 0; i < 8; i++)
#pragma unroll
        for (int j = 0; j < 4; j++) acc[i][j] = 0ull;

    for (int kc = 0; kc < CDIM; kc += 32) {
        __syncthreads();
        for (int idx = tid; idx < 128 * 32; idx += 256) {
            int r = idx >> 5, kk = idx & 31;
            Xs[kk][r] = x[(size_t)(n0 + r) * CDIM + kc + kk];
        }
        for (int idx = tid; idx < 32 * HDIM; idx += 256) {
            int kk = idx >> 7, col = idx & 127;
            int kr = kc + kk;
            float w = W1[(size_t)(CDIM + kr) * HDIM + col];
            if (isP) w = W1[(size_t)kr * HDIM + col] - w;
            Ws[kk][col] = w;
        }
        __syncthreads();
#pragma unroll 8
        for (int kk = 0; kk < 32; kk++)
            micro_step(&Xs[kk][0], &Ws[kk][0], ty * 8, tx * 8, acc);
    }
    float outv[8][8];
    unpack_acc(acc, outv);
    float* O = isP ? g_p[st] : g_q[st];
    float bj[8];
#pragma unroll
    for (int j = 0; j < 8; j++) bj[j] = isP ? B1[tx * 8 + j] : 0.f;
#pragma unroll
    for (int i = 0; i < 8; i++) {
        size_t row = (size_t)(n0 + ty * 8 + i) * HDIM + tx * 8;
        *(float4*)&O[row]     = make_float4(outv[i][0] + bj[0], outv[i][1] + bj[1],
                                            outv[i][2] + bj[2], outv[i][3] + bj[3]);
        *(float4*)&O[row + 4] = make_float4(outv[i][4] + bj[4], outv[i][5] + bj[5],
                                            outv[i][6] + bj[6], outv[i][7] + bj[7]);
    }
}

// ---------------------------------------------------------------------------
// 5: BN1 statistics
// ---------------------------------------------------------------------------
__global__ void k_bn1stats() {
    const int h = threadIdx.x;
    const int node0 = blockIdx.x * 32;
    float s0 = 0.f, q0 = 0.f, s1 = 0.f, q1 = 0.f;
    for (int nl = 0; nl < 32; nl++) {
        int n = node0 + nl;
        float p0 = g_p[0][(size_t)n * HDIM + h];
        float p1 = g_p[1][(size_t)n * HDIM + h];
        for (int k = 0; k < KNEIGH; k++) {
            int j = g_idx[(size_t)n * KNEIGH + k];
            float a = p0 + g_q[0][(size_t)j * HDIM + h];
            float b = p1 + g_q[1][(size_t)j * HDIM + h];
            s0 += a; q0 += a * a;
            s1 += b; q1 += b * b;
        }
    }
    atomicAdd(&g_bn1_sum[0][h], s0); atomicAdd(&g_bn1_sq[0][h], q0);
    atomicAdd(&g_bn1_sum[1][h], s1); atomicAdd(&g_bn1_sq[1][h], q1);
}

// ---------------------------------------------------------------------------
// 6: BN finalize
// ---------------------------------------------------------------------------
__global__ void k_bnfin(int which, int st, const float* __restrict__ g,
                        const float* __restrict__ be, float invN) {
    int h = threadIdx.x;
    float s, q;
    if (which == 0)      { s = g_bn1_sum[st][h]; q = g_bn1_sq[st][h]; }
    else if (which == 1) { s = g_bn2_sum[st][h]; q = g_bn2_sq[st][h]; }
    else                 { s = g_bnF_sum[h];     q = g_bnF_sq[h]; }
    float m   = s * invN;
    float var = fmaxf(q * invN - m * m, 0.f);
    float a   = g[h] * rsqrtf(var + BN_EPS);
    float c   = be[h] - m * a;
    if (which == 0)      { g_a1[st][h] = a; g_c1[st][h] = c; }
    else if (which == 1) { g_a2[st][h] = a; g_c2[st][h] = c; }
    else                 { g_aF[h] = a;     g_cF[h] = c; }
}

// ---------------------------------------------------------------------------
// 6b: prep W2^T split bf16 hi/lo, row-major [n][k] pitch BKP (raw smem image)
// ---------------------------------------------------------------------------
__global__ void k_w2prep(const float* __restrict__ sW2, const float* __restrict__ tW2) {
    const int st = blockIdx.x;
    const float* W2 = st ? tW2 : sW2;
    __nv_bfloat16* H = (__nv_bfloat16*)g_w2t_hi[st];
    __nv_bfloat16* L = (__nv_bfloat16*)g_w2t_lo[st];
    for (int lin = threadIdx.x; lin < HDIM * HDIM; lin += blockDim.x) {
        int n = lin & 127, k = lin >> 7;
        float w = W2[(size_t)k * HDIM + n];
        __nv_bfloat16 hi = __float2bfloat16_rn(w);
        __nv_bfloat16 lo = __float2bfloat16_rn(w - __bfloat162float(hi));
        H[n * BKP + k] = hi;
        L[n * BKP + k] = lo;
    }
}

// ---------------------------------------------------------------------------
// 7: edge GEMM on mma.sync bf16 (split hi/lo, 3 passes):
//    z = relu(bn1(p[n]+q[j])), h2 = z @ W2 + b2; per-node max/min + BN2 stats.
//    Block = 8 nodes (128 edge rows) x 128 cols, K=128. 8 warps, warp tile 32x64.
// ---------------------------------------------------------------------------
__global__ __launch_bounds__(256)
void k_edge_mma(const float* __restrict__ sb2v, const float* __restrict__ tb2v) {
    extern __shared__ __nv_bfloat16 dsm[];
    __shared__ int   sidx[128];
    __shared__ float s_sum[128], s_sq[128], b2s[128];

    const int st = blockIdx.z;
    const int node0 = blockIdx.x * 8;
    const int tid = threadIdx.x;
    const int wid = tid >> 5, lane = tid & 31;
    const int warp_m = wid & 3, warp_n = wid >> 2;
    const float* B2 = st ? tb2v : sb2v;
    const float* P  = g_p[st];
    const float* Q  = g_q[st];
    const float* A1 = g_a1[st];
    const float* C1 = g_c1[st];

    __nv_bfloat16* Ahi = dsm;
    __nv_bfloat16* Alo = Ahi + HDIM * BKP;
    __nv_bfloat16* Bhi = Alo + HDIM * BKP;
    __nv_bfloat16* Blo = Bhi + HDIM * BKP;

    if (tid < 128) {
        sidx[tid]  = g_idx[(size_t)node0 * KNEIGH + tid];
        s_sum[tid] = 0.f; s_sq[tid] = 0.f;
        b2s[tid]   = B2[tid];
    }

    // B tiles: linear copy (gmem holds the exact padded image)
    {
        const uint4* srch = (const uint4*)g_w2t_hi[st];
        const uint4* srcl = (const uint4*)g_w2t_lo[st];
        uint4* dsth = (uint4*)Bhi;
        uint4* dstl = (uint4*)Blo;
        for (int i = tid; i < W2T_BYTES / 16; i += 256) { dsth[i] = srch[i]; dstl[i] = srcl[i]; }
    }

    // A tile: gather + BN1 + ReLU + hi/lo split, row-major pitch BKP
    {
        int e = tid >> 1, half = tid & 1, k0 = half * 64;
        int n = node0 + (e >> 4);
        int j = sidx[e];
        const float4* Pr = (const float4*)(P + (size_t)n * HDIM + k0);
        const float4* Qr = (const float4*)(Q + (size_t)j * HDIM + k0);
        const float4* Av = (const float4*)(A1 + k0);
        const float4* Cv = (const float4*)(C1 + k0);
        __nv_bfloat16* ah = Ahi + e * BKP + k0;
        __nv_bfloat16* al = Alo + e * BKP + k0;
#pragma unroll
        for (int i = 0; i < 16; i++) {
            float4 pv = Pr[i], qv = Qr[i], av = Av[i], cv = Cv[i];
            float z0 = fmaxf(fmaf(av.x, pv.x + qv.x, cv.x), 0.f);
            float z1 = fmaxf(fmaf(av.y, pv.y + qv.y, cv.y), 0.f);
            float z2 = fmaxf(fmaf(av.z, pv.z + qv.z, cv.z), 0.f);
            float z3 = fmaxf(fmaf(av.w, pv.w + qv.w, cv.w), 0.f);
            __nv_bfloat16 h0 = __float2bfloat16_rn(z0), h1 = __float2bfloat16_rn(z1);
            __nv_bfloat16 h2 = __float2bfloat16_rn(z2), h3 = __float2bfloat16_rn(z3);
            __nv_bfloat162 th0; th0.x = h0; th0.y = h1;
            __nv_bfloat162 th1; th1.x = h2; th1.y = h3;
            __nv_bfloat162 tl0; tl0.x = __float2bfloat16_rn(z0 - __bfloat162float(h0));
            tl0.y = __float2bfloat16_rn(z1 - __bfloat162float(h1));
            __nv_bfloat162 tl1; tl1.x = __float2bfloat16_rn(z2 - __bfloat162float(h2));
            tl1.y = __float2bfloat16_rn(z3 - __bfloat162float(h3));
            *(__nv_bfloat162*)(ah + i * 4)     = th0;
            *(__nv_bfloat162*)(ah + i * 4 + 2) = th1;
            *(__nv_bfloat162*)(al + i * 4)     = tl0;
            *(__nv_bfloat162*)(al + i * 4 + 2) = tl1;
        }
    }
    __syncthreads();

    // mainloop: 3 passes x 8 K-steps, warp tile 32x64 (2 m-tiles x 8 n-tiles)
    float acc[2][8][4];
#pragma unroll
    for (int mt = 0; mt < 2; mt++)
#pragma unroll
        for (int nt = 0; nt < 8; nt++)
#pragma unroll
            for (int r = 0; r < 4; r++) acc[mt][nt][r] = 0.f;

    const int arow = warp_m * 32 + (lane >> 2);
    const int acol = (lane & 3) * 2;
    const int brow = warp_n * 64 + (lane >> 2);

#pragma unroll
    for (int pass = 0; pass < 3; pass++) {
        const __nv_bfloat16* As = (pass == 2) ? Alo : Ahi;
        const __nv_bfloat16* Bs = (pass == 1) ? Blo : Bhi;
#pragma unroll
        for (int k8 = 0; k8 < 8; k8++) {
            int kk = k8 * 16 + acol;
            uint32_t afr[2][4];
#pragma unroll
            for (int mt = 0; mt < 2; mt++) {
                const __nv_bfloat16* ap = As + (size_t)(arow + mt * 16) * BKP + kk;
                afr[mt][0] = *(const uint32_t*)(ap);
                afr[mt][1] = *(const uint32_t*)(ap + 8 * BKP);
                afr[mt][2] = *(const uint32_t*)(ap + 8);
                afr[mt][3] = *(const uint32_t*)(ap + 8 * BKP + 8);
            }
            uint32_t bfr[8][2];
#pragma unroll
            for (int nt = 0; nt < 8; nt++) {
                const __nv_bfloat16* bp = Bs + (size_t)(brow + nt * 8) * BKP + kk;
                bfr[nt][0] = *(const uint32_t*)(bp);
                bfr[nt][1] = *(const uint32_t*)(bp + 8);
            }
#pragma unroll
            for (int mt = 0; mt < 2; mt++)
#pragma unroll
                for (int nt = 0; nt < 8; nt++)
                    mma16816(acc[mt][nt], afr[mt], bfr[nt]);
        }
    }

    // epilogue: each m-tile (16 rows) is exactly one node's 16 edges
#pragma unroll
    for (int mt = 0; mt < 2; mt++) {
        const int node = node0 + warp_m * 2 + mt;
#pragma unroll
        for (int nt = 0; nt < 8; nt++) {
            const int col = warp_n * 64 + nt * 8 + (lane & 3) * 2;
            float bb0 = b2s[col], bb1 = b2s[col + 1];
            float v0 = acc[mt][nt][0] + bb0, v1 = acc[mt][nt][1] + bb1;
            float v2 = acc[mt][nt][2] + bb0, v3 = acc[mt][nt][3] + bb1;
            float mx0 = fmaxf(v0, v2), mx1 = fmaxf(v1, v3);
            float mn0 = fminf(v0, v2), mn1 = fminf(v1, v3);
            float sm0 = v0 + v2,       sm1 = v1 + v3;
            float sq0 = v0 * v0 + v2 * v2, sq1 = v1 * v1 + v3 * v3;
#pragma unroll
            for (int off = 4; off <= 16; off <<= 1) {
                mx0 = fmaxf(mx0, __shfl_xor_sync(0xffffffffu, mx0, off));
                mx1 = fmaxf(mx1, __shfl_xor_sync(0xffffffffu, mx1, off));
                mn0 = fminf(mn0, __shfl_xor_sync(0xffffffffu, mn0, off));
                mn1 = fminf(mn1, __shfl_xor_sync(0xffffffffu, mn1, off));
                sm0 += __shfl_xor_sync(0xffffffffu, sm0, off);
                sm1 += __shfl_xor_sync(0xffffffffu, sm1, off);
                sq0 += __shfl_xor_sync(0xffffffffu, sq0, off);
                sq1 += __shfl_xor_sync(0xffffffffu, sq1, off);
            }
            if (lane < 4) {
                size_t o = (size_t)node * HDIM + col;
                g_aggmax[st][o]     = mx0;
                g_aggmax[st][o + 1] = mx1;
                g_aggmin[st][o]     = mn0;
                g_aggmin[st][o + 1] = mn1;
                atomicAdd(&s_sum[col], sm0);  atomicAdd(&s_sum[col + 1], sm1);
                atomicAdd(&s_sq[col],  sq0);  atomicAdd(&s_sq[col + 1],  sq1);
            }
        }
    }
    __syncthreads();
    if (tid < 128) {
        atomicAdd(&g_bn2_sum[st][tid], s_sum[tid]);
        atomicAdd(&g_bn2_sq[st][tid], s_sq[tid]);
    }
}

// ---------------------------------------------------------------------------
// 8: final GEMM
// ---------------------------------------------------------------------------
__global__ __launch_bounds__(256) void k_final(const float* __restrict__ fW, const float* __restrict__ fb) {
    __shared__ float Fs[32][LDW];
    __shared__ float Ws[32][LDW];
    __shared__ float s_sum[HDIM], s_sq[HDIM];
    const int n0 = blockIdx.x * 128;
    const int tid = threadIdx.x, ty = tid >> 4, tx = tid & 15;
    if (tid < 128) { s_sum[tid] = 0.f; s_sq[tid] = 0.f; }
    ull acc[8][4];
#pragma unroll
    for (int i = 0; i < 8; i++)
#pragma unroll
        for (int j = 0; j < 4; j++) acc[i][j] = 0ull;

    for (int kc = 0; kc < 2 * HDIM; kc += 32) {
        __syncthreads();
        for (int idx = tid; idx < 128 * 32; idx += 256) {
            int nl = idx >> 5, kk = idx & 31;
            int kf = kc + kk;
            int st = kf >> 7, ch = kf & 127;
            float a2 = g_a2[st][ch], c2 = g_c2[st][ch];
            size_t o = (size_t)(n0 + nl) * HDIM + ch;
            float v = (a2 >= 0.f) ? g_aggmax[st][o] : g_aggmin[st][o];
            Fs[kk][nl] = fmaxf(fmaf(a2, v, c2), 0.f);
        }
        for (int idx = tid; idx < 32 * HDIM; idx += 256) {
            int kk = idx >> 7, col = idx & 127;
            Ws[kk][col] = fW[(size_t)(kc + kk) * HDIM + col];
        }
        __syncthreads();
#pragma unroll 8
        for (int kk = 0; kk < 32; kk++)
            micro_step(&Fs[kk][0], &Ws[kk][0], ty * 8, tx * 8, acc);
    }
    float outv[8][8];
    unpack_acc(acc, outv);
    float bj[8];
#pragma unroll
    for (int j = 0; j < 8; j++) bj[j] = fb[tx * 8 + j];
#pragma unroll
    for (int i = 0; i < 8; i++)
#pragma unroll
        for (int j = 0; j < 8; j++) outv[i][j] += bj[j];
#pragma unroll
    for (int i = 0; i < 8; i++) {
        size_t row = (size_t)(n0 + ty * 8 + i) * HDIM + tx * 8;
        *(float4*)&g_hF[row]     = make_float4(outv[i][0], outv[i][1], outv[i][2], outv[i][3]);
        *(float4*)&g_hF[row + 4] = make_float4(outv[i][4], outv[i][5], outv[i][6], outv[i][7]);
    }
#pragma unroll
    for (int j = 0; j < 8; j++) {
        float cs = 0.f, cq = 0.f;
#pragma unroll
        for (int i = 0; i < 8; i++) { float v = outv[i][j]; cs += v; cq += v * v; }
        cs += __shfl_xor_sync(0xffffffffu, cs, 16);
        cq += __shfl_xor_sync(0xffffffffu, cq, 16);
        if ((ty & 1) == 0) {
            int col = tx * 8 + j;
            atomicAdd(&s_sum[col], cs);
            atomicAdd(&s_sq[col], cq);
        }
    }
    __syncthreads();
    if (tid < 128) {
        atomicAdd(&g_bnF_sum[tid], s_sum[tid]);
        atomicAdd(&g_bnF_sq[tid], s_sq[tid]);
    }
}

// ---------------------------------------------------------------------------
// 9: output elementwise
// ---------------------------------------------------------------------------
__global__ void k_out(float* __restrict__ out) {
    int idx = blockIdx.x * 256 + threadIdx.x;
    int col = idx & 127;
    out[idx] = fmaxf(fmaf(g_aF[col], g_hF[idx], g_cF[col]), 0.f);
}

// ---------------------------------------------------------------------------
// launcher
// ---------------------------------------------------------------------------
extern "C" void kernel_launch(void* const* d_in, const int* in_sizes, int n_in,
                              void* d_out, int out_size) {
    (void)in_sizes; (void)n_in; (void)out_size;
    const float* x     = (const float*)d_in[0];
    const float* s_W1  = (const float*)d_in[2];
    const float* s_b1  = (const float*)d_in[3];
    const float* s_g1  = (const float*)d_in[4];
    const float* s_be1 = (const float*)d_in[5];
    const float* s_W2  = (const float*)d_in[6];
    const float* s_b2  = (const float*)d_in[7];
    const float* s_g2  = (const float*)d_in[8];
    const float* s_be2 = (const float*)d_in[9];
    const float* t_W1  = (const float*)d_in[10];
    const float* t_b1  = (const float*)d_in[11];
    const float* t_g1  = (const float*)d_in[12];
    const float* t_be1 = (const float*)d_in[13];
    const float* t_W2  = (const float*)d_in[14];
    const float* t_b2  = (const float*)d_in[15];
    const float* t_g2  = (const float*)d_in[16];
    const float* t_be2 = (const float*)d_in[17];
    const float* f_W   = (const float*)d_in[18];
    const float* f_b   = (const float*)d_in[19];
    const float* f_g   = (const float*)d_in[20];
    const float* f_be  = (const float*)d_in[21];
    float* out = (float*)d_out;

    const float invE  = 1.f / (float)EDGES;
    const float invNT = 1.f / (float)NT;

    cudaFuncSetAttribute(k_edge_mma, cudaFuncAttributeMaxDynamicSharedMemorySize, EDGE_SMEM);

    k_zero<<<1, 128>>>();
    k_sq<<<NT / 8, 256>>>(x);
    k_d2<<<dim3(NNODE / 128, NNODE / 128, BBATCH), 256>>>(x);
    k_topk<<<NT / TKW, 32 * TKW>>>();
    k_pq<<<dim3(NT / 128, 1, 4), 256>>>(x, s_W1, s_b1, t_W1, t_b1);
    k_bn1stats<<<NT / 32, 128>>>();
    k_bnfin<<<1, 128>>>(0, 0, s_g1, s_be1, invE);
    k_bnfin<<<1, 128>>>(0, 1, t_g1, t_be1, invE);
    k_w2prep<<<2, 256>>>(s_W2, t_W2);
    k_edge_mma<<<dim3(NT / 8, 1, 2), 256, EDGE_SMEM>>>(s_b2, t_b2);
    k_bnfin<<<1, 128>>>(1, 0, s_g2, s_be2, invE);
    k_bnfin<<<1, 128>>>(1, 1, t_g2, t_be2, invE);
    k_final<<<NT / 128, 256>>>(f_W, f_b);
    k_bnfin<<<1, 128>>>(2, 0, f_g, f_be, invNT);
    k_out<<<(NT * HDIM) / 256, 256>>>(out);
}

// round 14
// speedup vs baseline: 1.5494x; 1.0100x over previous
#include <cuda_runtime.h>
#include <cuda_bf16.h>
#include <cstdint>

#define BBATCH 16
#define NNODE  2048
#define CDIM   64
#define HDIM   128
#define KNEIGH 16
#define NT     (BBATCH*NNODE)        /* 32768 nodes  */
#define EDGES  (NT*KNEIGH)           /* 524288 edges */
#define BN_EPS 1e-5f
#define LDW    132                   /* smem tile pitch (floats) for FFMA GEMMs */
#define TKW    4                     /* top-k: rows (warps) per block */
#define BKP    136                   /* bf16 tile pitch (elements) for edge mma tiles */
#define W2T_BYTES (HDIM*BKP*2)       /* 34816 bytes per hi/lo tile */
#define EDGE_SMEM (4*W2T_BYTES)      /* 139264 */
#define DKP    68                    /* fp32 tile pitch for d2 tf32 tiles (K=64) */
#define D2_SMEM (4*HDIM*DKP*4)       /* 139264 */

typedef unsigned long long ull;

// ---------------------------------------------------------------------------
// Static device scratch (no runtime allocation allowed)
// ---------------------------------------------------------------------------
__device__ float g_sq[NT];
__device__ float g_d2[(size_t)BBATCH * NNODE * NNODE];        // 256 MB
__device__ int   g_idx[EDGES];
__device__ __align__(16) float g_p[2][(size_t)NT * HDIM];
__device__ __align__(16) float g_q[2][(size_t)NT * HDIM];
__device__ float g_bn1_sum[2][HDIM], g_bn1_sq[2][HDIM];
__device__ __align__(16) float g_a1[2][HDIM], g_c1[2][HDIM];
__device__ __align__(16) float g_aggmax[2][(size_t)NT * HDIM];
__device__ __align__(16) float g_aggmin[2][(size_t)NT * HDIM];
__device__ float g_bn2_sum[2][HDIM], g_bn2_sq[2][HDIM];
__device__ float g_a2[2][HDIM], g_c2[2][HDIM];
__device__ __align__(16) float g_hF[(size_t)NT * HDIM];
__device__ float g_bnF_sum[HDIM], g_bnF_sq[HDIM];
__device__ float g_aF[HDIM], g_cF[HDIM];
// W2^T split into bf16 hi/lo, row-major [n][k] with pitch BKP (raw smem image)
__device__ __align__(16) unsigned char g_w2t_hi[2][W2T_BYTES];
__device__ __align__(16) unsigned char g_w2t_lo[2][W2T_BYTES];

// ---------------------------------------------------------------------------
// f32x2 packed-FMA helpers
// ---------------------------------------------------------------------------
__device__ __forceinline__ ull pk2(float lo, float hi) {
    ull r; asm("mov.b64 %0, {%1, %2};" : "=l"(r) : "f"(lo), "f"(hi)); return r;
}
__device__ __forceinline__ void fma2(ull &d, ull a, ull b) {
    asm("fma.rn.f32x2 %0, %1, %2, %0;" : "+l"(d) : "l"(a), "l"(b));
}
__device__ __forceinline__ float2 up2(ull v) {
    float2 f; asm("mov.b64 {%0, %1}, %2;" : "=f"(f.x), "=f"(f.y) : "l"(v)); return f;
}

__device__ __forceinline__ void micro_step(const float* __restrict__ Arow,
                                           const float* __restrict__ Brow,
                                           int ty8, int tx8, ull acc[8][4]) {
    float4 a0 = *(const float4*)(Arow + ty8);
    float4 a1 = *(const float4*)(Arow + ty8 + 4);
    float4 b0 = *(const float4*)(Brow + tx8);
    float4 b1 = *(const float4*)(Brow + tx8 + 4);
    ull bv0 = pk2(b0.x, b0.y), bv1 = pk2(b0.z, b0.w);
    ull bv2 = pk2(b1.x, b1.y), bv3 = pk2(b1.z, b1.w);
    float av[8] = {a0.x, a0.y, a0.z, a0.w, a1.x, a1.y, a1.z, a1.w};
#pragma unroll
    for (int i = 0; i < 8; i++) {
        ull ai = pk2(av[i], av[i]);
        fma2(acc[i][0], ai, bv0);
        fma2(acc[i][1], ai, bv1);
        fma2(acc[i][2], ai, bv2);
        fma2(acc[i][3], ai, bv3);
    }
}

__device__ __forceinline__ void unpack_acc(ull acc[8][4], float outv[8][8]) {
#pragma unroll
    for (int i = 0; i < 8; i++)
#pragma unroll
        for (int j2 = 0; j2 < 4; j2++) {
            float2 u = up2(acc[i][j2]);
            outv[i][2*j2]   = u.x;
            outv[i][2*j2+1] = u.y;
        }
}

// mma.sync bf16 (sm_80 baseline feature)
__device__ __forceinline__ void mma16816(float* d, const uint32_t* a, const uint32_t* b) {
    asm volatile(
        "mma.sync.aligned.m16n8k16.row.col.f32.bf16.bf16.f32 "
        "{%0,%1,%2,%3}, {%4,%5,%6,%7}, {%8,%9}, {%0,%1,%2,%3};"
        : "+f"(d[0]), "+f"(d[1]), "+f"(d[2]), "+f"(d[3])
        : "r"(a[0]), "r"(a[1]), "r"(a[2]), "r"(a[3]), "r"(b[0]), "r"(b[1]));
}

// mma.sync tf32 (sm_80 baseline feature)
__device__ __forceinline__ void mma1688(float* d, const uint32_t* a, const uint32_t* b) {
    asm volatile(
        "mma.sync.aligned.m16n8k8.row.col.f32.tf32.tf32.f32 "
        "{%0,%1,%2,%3}, {%4,%5,%6,%7}, {%8,%9}, {%0,%1,%2,%3};"
        : "+f"(d[0]), "+f"(d[1]), "+f"(d[2]), "+f"(d[3])
        : "r"(a[0]), "r"(a[1]), "r"(a[2]), "r"(a[3]), "r"(b[0]), "r"(b[1]));
}

// split a float into bf16 hi/lo pair packed as __nv_bfloat162 stores
__device__ __forceinline__ void split2(float z0, float z1,
                                       __nv_bfloat162 &hi, __nv_bfloat162 &lo) {
    __nv_bfloat16 h0 = __float2bfloat16_rn(z0), h1 = __float2bfloat16_rn(z1);
    hi.x = h0; hi.y = h1;
    lo.x = __float2bfloat16_rn(z0 - __bfloat162float(h0));
    lo.y = __float2bfloat16_rn(z1 - __bfloat162float(h1));
}

// tf32 split: hi = tf32(v), lo = tf32(v - hi)  (3xTF32 scheme)
__device__ __forceinline__ uint32_t tf32_of(float v) {
    uint32_t r; asm("cvt.rna.tf32.f32 %0, %1;" : "=r"(r) : "f"(v)); return r;
}
__device__ __forceinline__ void tf32split(float v, float &h, float &l) {
    uint32_t hr = tf32_of(v);
    h = __uint_as_float(hr);
    l = __uint_as_float(tf32_of(v - h));
}

// ---------------------------------------------------------------------------
// 0: zero accumulators
// ---------------------------------------------------------------------------
__global__ void k_zero() {
    int t = threadIdx.x;
    if (t < HDIM) {
        g_bn1_sum[0][t] = 0.f; g_bn1_sum[1][t] = 0.f;
        g_bn1_sq[0][t]  = 0.f; g_bn1_sq[1][t]  = 0.f;
        g_bn2_sum[0][t] = 0.f; g_bn2_sum[1][t] = 0.f;
        g_bn2_sq[0][t]  = 0.f; g_bn2_sq[1][t]  = 0.f;
        g_bnF_sum[t]    = 0.f; g_bnF_sq[t]     = 0.f;
    }
}

// ---------------------------------------------------------------------------
// 1: per-node squared norms
// ---------------------------------------------------------------------------
__global__ void k_sq(const float* __restrict__ x) {
    int w    = (blockIdx.x * blockDim.x + threadIdx.x) >> 5;
    int lane = threadIdx.x & 31;
    if (w >= NT) return;
    float v0 = x[(size_t)w * CDIM + lane];
    float v1 = x[(size_t)w * CDIM + 32 + lane];
    float s = v0 * v0 + v1 * v1;
#pragma unroll
    for (int off = 16; off; off >>= 1) s += __shfl_xor_sync(0xffffffffu, s, off);
    if (lane == 0) g_sq[w] = s;
}

// ---------------------------------------------------------------------------
// 2: pairwise squared distances via 3xTF32 Gram matrix (near-fp32 accuracy)
//    d2[i][j] = sq[i] + sq[j] - 2 * (x_i . x_j)
// ---------------------------------------------------------------------------
__global__ __launch_bounds__(256)
void k_d2_mma(const float* __restrict__ x) {
    extern __shared__ float dsmf[];
    __shared__ float sqi_s[128], sqj_s[128];

    const int b  = blockIdx.z;
    const int i0 = blockIdx.y * 128, j0 = blockIdx.x * 128;
    const float* X = x + (size_t)b * NNODE * CDIM;
    const int tid = threadIdx.x;
    const int lane = tid & 31, wid = tid >> 5;
    const int warp_m = wid & 3, warp_n = wid >> 2;

    float* Ahi = dsmf;                       // [128][DKP] fp32 (tf32 values)
    float* Alo = Ahi + HDIM * DKP;
    float* Bhi = Alo + HDIM * DKP;
    float* Blo = Bhi + HDIM * DKP;

    if (tid < 128) {
        sqi_s[tid] = g_sq[b * NNODE + i0 + tid];
        sqj_s[tid] = g_sq[b * NNODE + j0 + tid];
    }

    // load + tf32-split both 128x64 tiles (float4 granularity; DKP=68 keeps 16B align)
    for (int idx = tid; idx < 128 * 16; idx += 256) {
        int row = idx >> 4, c4 = (idx & 15) * 4;
        float4 vi = *(const float4*)(X + (size_t)(i0 + row) * CDIM + c4);
        float4 vj = *(const float4*)(X + (size_t)(j0 + row) * CDIM + c4);
        float4 h, l;
        tf32split(vi.x, h.x, l.x); tf32split(vi.y, h.y, l.y);
        tf32split(vi.z, h.z, l.z); tf32split(vi.w, h.w, l.w);
        *(float4*)(Ahi + row * DKP + c4) = h;
        *(float4*)(Alo + row * DKP + c4) = l;
        tf32split(vj.x, h.x, l.x); tf32split(vj.y, h.y, l.y);
        tf32split(vj.z, h.z, l.z); tf32split(vj.w, h.w, l.w);
        *(float4*)(Bhi + row * DKP + c4) = h;
        *(float4*)(Blo + row * DKP + c4) = l;
    }
    __syncthreads();

    float acc[2][8][4];
#pragma unroll
    for (int mt = 0; mt < 2; mt++)
#pragma unroll
        for (int nt = 0; nt < 8; nt++)
#pragma unroll
            for (int r = 0; r < 4; r++) acc[mt][nt][r] = 0.f;

    const int arow = warp_m * 32 + (lane >> 2);
    const int kk4  = lane & 3;                 // k offset within 8-wide k-step
    const int brow = warp_n * 64 + (lane >> 2);

#pragma unroll
    for (int pass = 0; pass < 3; pass++) {
        const float* As = (pass == 2) ? Alo : Ahi;
        const float* Bs = (pass == 1) ? Blo : Bhi;
#pragma unroll
        for (int k8 = 0; k8 < 8; k8++) {
            int kk = k8 * 8 + kk4;
            uint32_t afr[2][4];
#pragma unroll
            for (int mt = 0; mt < 2; mt++) {
                const float* ap = As + (size_t)(arow + mt * 16) * DKP + kk;
                afr[mt][0] = *(const uint32_t*)(ap);
                afr[mt][1] = *(const uint32_t*)(ap + 8 * DKP);
                afr[mt][2] = *(const uint32_t*)(ap + 4);
                afr[mt][3] = *(const uint32_t*)(ap + 8 * DKP + 4);
            }
            uint32_t bfr[8][2];
#pragma unroll
            for (int nt = 0; nt < 8; nt++) {
                const float* bp = Bs + (size_t)(brow + nt * 8) * DKP + kk;
                bfr[nt][0] = *(const uint32_t*)(bp);
                bfr[nt][1] = *(const uint32_t*)(bp + 4);
            }
#pragma unroll
            for (int mt = 0; mt < 2; mt++)
#pragma unroll
                for (int nt = 0; nt < 8; nt++)
                    mma1688(acc[mt][nt], afr[mt], bfr[nt]);
        }
    }

    // epilogue: d2 = sqi + sqj - 2*G, float2 stores
#pragma unroll
    for (int mt = 0; mt < 2; mt++) {
        int r0 = warp_m * 32 + mt * 16 + (lane >> 2);
#pragma unroll
        for (int nt = 0; nt < 8; nt++) {
            int c0 = warp_n * 64 + nt * 8 + (lane & 3) * 2;
            float sj0 = sqj_s[c0], sj1 = sqj_s[c0 + 1];
            {
                float si = sqi_s[r0];
                float2 o; o.x = si + sj0 - 2.f * acc[mt][nt][0];
                o.y = si + sj1 - 2.f * acc[mt][nt][1];
                *(float2*)&g_d2[((size_t)(b * NNODE + i0 + r0)) * NNODE + j0 + c0] = o;
            }
            {
                float si = sqi_s[r0 + 8];
                float2 o; o.x = si + sj0 - 2.f * acc[mt][nt][2];
                o.y = si + sj1 - 2.f * acc[mt][nt][3];
                *(float2*)&g_d2[((size_t)(b * NNODE + i0 + r0 + 8)) * NNODE + j0 + c0] = o;
            }
        }
    }
}

// ---------------------------------------------------------------------------
// 3: top-K smallest per row (warp per row)
// ---------------------------------------------------------------------------
__global__ __launch_bounds__(32 * TKW) void k_topk() {
    __shared__ float vals[TKW][NNODE];
    const int warp = threadIdx.x >> 5, lane = threadIdx.x & 31;
    const int row  = blockIdx.x * TKW + warp;
    const size_t rowoff = (size_t)row * NNODE;
    const int b = row >> 11;
    float* v = vals[warp];

    for (int j = lane; j < NNODE; j += 32) v[j] = g_d2[rowoff + j];
    __syncwarp();

    float bm = 3.0e38f; int bi = 0x7fffffff;
#pragma unroll 16
    for (int j = lane; j < NNODE; j += 32) {
        float x = v[j];
        if (x < bm) { bm = x; bi = j; }
    }

    for (int k = 0; k < KNEIGH; k++) {
        float wv = bm; int wi = bi;
#pragma unroll
        for (int off = 16; off; off >>= 1) {
            float ov = __shfl_xor_sync(0xffffffffu, wv, off);
            int   oi = __shfl_xor_sync(0xffffffffu, wi, off);
            if (ov < wv || (ov == wv && oi < wi)) { wv = ov; wi = oi; }
        }
        if (lane == 0) g_idx[(size_t)row * KNEIGH + k] = b * NNODE + wi;
        if ((wi & 31) == lane) {
            v[wi] = 3.0e38f;
            bm = 3.0e38f; bi = 0x7fffffff;
#pragma unroll 16
            for (int j = lane; j < NNODE; j += 32) {
                float x = v[j];
                if (x < bm) { bm = x; bi = j; }
            }
        }
        __syncwarp();
    }
}

// ---------------------------------------------------------------------------
// 4: p/q GEMMs
// ---------------------------------------------------------------------------
__global__ __launch_bounds__(256) void k_pq(const float* __restrict__ x,
                                            const float* __restrict__ sW1, const float* __restrict__ sb1,
                                            const float* __restrict__ tW1, const float* __restrict__ tb1) {
    __shared__ float Xs[32][LDW];
    __shared__ float Ws[32][LDW];
    const int z   = blockIdx.z;
    const int st  = z >> 1;
    const bool isP = (z & 1) == 0;
    const float* W1 = st ? tW1 : sW1;
    const float* B1 = st ? tb1 : sb1;
    const int n0 = blockIdx.x * 128;
    const int tid = threadIdx.x, ty = tid >> 4, tx = tid & 15;
    ull acc[8][4];
#pragma unroll
    for (int i = 0; i < 8; i++)
#pragma unroll
        for (int j = 0; j < 4; j++) acc[i][j] = 0ull;

    for (int kc = 0; kc < CDIM; kc += 32) {
        __syncthreads();
        for (int idx = tid; idx < 128 * 32; idx += 256) {
            int r = idx >> 5, kk = idx & 31;
            Xs[kk][r] = x[(size_t)(n0 + r) * CDIM + kc + kk];
        }
        for (int idx = tid; idx < 32 * HDIM; idx += 256) {
            int kk = idx >> 7, col = idx & 127;
            int kr = kc + kk;
            float w = W1[(size_t)(CDIM + kr) * HDIM + col];
            if (isP) w = W1[(size_t)kr * HDIM + col] - w;
            Ws[kk][col] = w;
        }
        __syncthreads();
#pragma unroll 8
        for (int kk = 0; kk < 32; kk++)
            micro_step(&Xs[kk][0], &Ws[kk][0], ty * 8, tx * 8, acc);
    }
    float outv[8][8];
    unpack_acc(acc, outv);
    float* O = isP ? g_p[st] : g_q[st];
    float bj[8];
#pragma unroll
    for (int j = 0; j < 8; j++) bj[j] = isP ? B1[tx * 8 + j] : 0.f;
#pragma unroll
    for (int i = 0; i < 8; i++) {
        size_t row = (size_t)(n0 + ty * 8 + i) * HDIM + tx * 8;
        *(float4*)&O[row]     = make_float4(outv[i][0] + bj[0], outv[i][1] + bj[1],
                                            outv[i][2] + bj[2], outv[i][3] + bj[3]);
        *(float4*)&O[row + 4] = make_float4(outv[i][4] + bj[4], outv[i][5] + bj[5],
                                            outv[i][6] + bj[6], outv[i][7] + bj[7]);
    }
}

// ---------------------------------------------------------------------------
// 5: BN1 statistics
// ---------------------------------------------------------------------------
__global__ void k_bn1stats() {
    const int h = threadIdx.x;
    const int node0 = blockIdx.x * 32;
    float s0 = 0.f, q0 = 0.f, s1 = 0.f, q1 = 0.f;
    for (int nl = 0; nl < 32; nl++) {
        int n = node0 + nl;
        float p0 = g_p[0][(size_t)n * HDIM + h];
        float p1 = g_p[1][(size_t)n * HDIM + h];
        for (int k = 0; k < KNEIGH; k++) {
            int j = g_idx[(size_t)n * KNEIGH + k];
            float a = p0 + g_q[0][(size_t)j * HDIM + h];
            float b = p1 + g_q[1][(size_t)j * HDIM + h];
            s0 += a; q0 += a * a;
            s1 += b; q1 += b * b;
        }
    }
    atomicAdd(&g_bn1_sum[0][h], s0); atomicAdd(&g_bn1_sq[0][h], q0);
    atomicAdd(&g_bn1_sum[1][h], s1); atomicAdd(&g_bn1_sq[1][h], q1);
}

// ---------------------------------------------------------------------------
// 6: BN finalize
// ---------------------------------------------------------------------------
__global__ void k_bnfin(int which, int st, const float* __restrict__ g,
                        const float* __restrict__ be, float invN) {
    int h = threadIdx.x;
    float s, q;
    if (which == 0)      { s = g_bn1_sum[st][h]; q = g_bn1_sq[st][h]; }
    else if (which == 1) { s = g_bn2_sum[st][h]; q = g_bn2_sq[st][h]; }
    else                 { s = g_bnF_sum[h];     q = g_bnF_sq[h]; }
    float m   = s * invN;
    float var = fmaxf(q * invN - m * m, 0.f);
    float a   = g[h] * rsqrtf(var + BN_EPS);
    float c   = be[h] - m * a;
    if (which == 0)      { g_a1[st][h] = a; g_c1[st][h] = c; }
    else if (which == 1) { g_a2[st][h] = a; g_c2[st][h] = c; }
    else                 { g_aF[h] = a;     g_cF[h] = c; }
}

// ---------------------------------------------------------------------------
// 6b: prep W2^T split bf16 hi/lo, row-major [n][k] pitch BKP (raw smem image)
// ---------------------------------------------------------------------------
__global__ void k_w2prep(const float* __restrict__ sW2, const float* __restrict__ tW2) {
    const int st = blockIdx.x;
    const float* W2 = st ? tW2 : sW2;
    __nv_bfloat16* H = (__nv_bfloat16*)g_w2t_hi[st];
    __nv_bfloat16* L = (__nv_bfloat16*)g_w2t_lo[st];
    for (int lin = threadIdx.x; lin < HDIM * HDIM; lin += blockDim.x) {
        int n = lin & 127, k = lin >> 7;
        float w = W2[(size_t)k * HDIM + n];
        __nv_bfloat16 hi = __float2bfloat16_rn(w);
        __nv_bfloat16 lo = __float2bfloat16_rn(w - __bfloat162float(hi));
        H[n * BKP + k] = hi;
        L[n * BKP + k] = lo;
    }
}

// ---------------------------------------------------------------------------
// 7: edge GEMM on mma.sync bf16 (split hi/lo, 3 passes)
// ---------------------------------------------------------------------------
__global__ __launch_bounds__(256)
void k_edge_mma(const float* __restrict__ sb2v, const float* __restrict__ tb2v) {
    extern __shared__ __nv_bfloat16 dsm[];
    __shared__ int   sidx[128];
    __shared__ float s_sum[128], s_sq[128], b2s[128];

    const int st = blockIdx.z;
    const int node0 = blockIdx.x * 8;
    const int tid = threadIdx.x;
    const int wid = tid >> 5, lane = tid & 31;
    const int warp_m = wid & 3, warp_n = wid >> 2;
    const float* B2 = st ? tb2v : sb2v;
    const float* P  = g_p[st];
    const float* Q  = g_q[st];
    const float* A1 = g_a1[st];
    const float* C1 = g_c1[st];

    __nv_bfloat16* Ahi = dsm;
    __nv_bfloat16* Alo = Ahi + HDIM * BKP;
    __nv_bfloat16* Bhi = Alo + HDIM * BKP;
    __nv_bfloat16* Blo = Bhi + HDIM * BKP;

    if (tid < 128) {
        sidx[tid]  = g_idx[(size_t)node0 * KNEIGH + tid];
        s_sum[tid] = 0.f; s_sq[tid] = 0.f;
        b2s[tid]   = B2[tid];
    }

    {
        const uint4* srch = (const uint4*)g_w2t_hi[st];
        const uint4* srcl = (const uint4*)g_w2t_lo[st];
        uint4* dsth = (uint4*)Bhi;
        uint4* dstl = (uint4*)Blo;
        for (int i = tid; i < W2T_BYTES / 16; i += 256) { dsth[i] = srch[i]; dstl[i] = srcl[i]; }
    }

    {
        int e = tid >> 1, half = tid & 1, k0 = half * 64;
        int n = node0 + (e >> 4);
        int j = sidx[e];
        const float4* Pr = (const float4*)(P + (size_t)n * HDIM + k0);
        const float4* Qr = (const float4*)(Q + (size_t)j * HDIM + k0);
        const float4* Av = (const float4*)(A1 + k0);
        const float4* Cv = (const float4*)(C1 + k0);
        __nv_bfloat16* ah = Ahi + e * BKP + k0;
        __nv_bfloat16* al = Alo + e * BKP + k0;
#pragma unroll
        for (int i = 0; i < 16; i++) {
            float4 pv = Pr[i], qv = Qr[i], av = Av[i], cv = Cv[i];
            float z0 = fmaxf(fmaf(av.x, pv.x + qv.x, cv.x), 0.f);
            float z1 = fmaxf(fmaf(av.y, pv.y + qv.y, cv.y), 0.f);
            float z2 = fmaxf(fmaf(av.z, pv.z + qv.z, cv.z), 0.f);
            float z3 = fmaxf(fmaf(av.w, pv.w + qv.w, cv.w), 0.f);
            __nv_bfloat162 h0, l0, h1, l1;
            split2(z0, z1, h0, l0); split2(z2, z3, h1, l1);
            *(__nv_bfloat162*)(ah + i * 4)     = h0;
            *(__nv_bfloat162*)(ah + i * 4 + 2) = h1;
            *(__nv_bfloat162*)(al + i * 4)     = l0;
            *(__nv_bfloat162*)(al + i * 4 + 2) = l1;
        }
    }
    __syncthreads();

    float acc[2][8][4];
#pragma unroll
    for (int mt = 0; mt < 2; mt++)
#pragma unroll
        for (int nt = 0; nt < 8; nt++)
#pragma unroll
            for (int r = 0; r < 4; r++) acc[mt][nt][r] = 0.f;

    const int arow = warp_m * 32 + (lane >> 2);
    const int acol = (lane & 3) * 2;
    const int brow = warp_n * 64 + (lane >> 2);

#pragma unroll
    for (int pass = 0; pass < 3; pass++) {
        const __nv_bfloat16* As = (pass == 2) ? Alo : Ahi;
        const __nv_bfloat16* Bs = (pass == 1) ? Blo : Bhi;
#pragma unroll
        for (int k8 = 0; k8 < 8; k8++) {
            int kk = k8 * 16 + acol;
            uint32_t afr[2][4];
#pragma unroll
            for (int mt = 0; mt < 2; mt++) {
                const __nv_bfloat16* ap = As + (size_t)(arow + mt * 16) * BKP + kk;
                afr[mt][0] = *(const uint32_t*)(ap);
                afr[mt][1] = *(const uint32_t*)(ap + 8 * BKP);
                afr[mt][2] = *(const uint32_t*)(ap + 8);
                afr[mt][3] = *(const uint32_t*)(ap + 8 * BKP + 8);
            }
            uint32_t bfr[8][2];
#pragma unroll
            for (int nt = 0; nt < 8; nt++) {
                const __nv_bfloat16* bp = Bs + (size_t)(brow + nt * 8) * BKP + kk;
                bfr[nt][0] = *(const uint32_t*)(bp);
                bfr[nt][1] = *(const uint32_t*)(bp + 8);
            }
#pragma unroll
            for (int mt = 0; mt < 2; mt++)
#pragma unroll
                for (int nt = 0; nt < 8; nt++)
                    mma16816(acc[mt][nt], afr[mt], bfr[nt]);
        }
    }

#pragma unroll
    for (int mt = 0; mt < 2; mt++) {
        const int node = node0 + warp_m * 2 + mt;
#pragma unroll
        for (int nt = 0; nt < 8; nt++) {
            const int col = warp_n * 64 + nt * 8 + (lane & 3) * 2;
            float bb0 = b2s[col], bb1 = b2s[col + 1];
            float v0 = acc[mt][nt][0] + bb0, v1 = acc[mt][nt][1] + bb1;
            float v2 = acc[mt][nt][2] + bb0, v3 = acc[mt][nt][3] + bb1;
            float mx0 = fmaxf(v0, v2), mx1 = fmaxf(v1, v3);
            float mn0 = fminf(v0, v2), mn1 = fminf(v1, v3);
            float sm0 = v0 + v2,       sm1 = v1 + v3;
            float sq0 = v0 * v0 + v2 * v2, sq1 = v1 * v1 + v3 * v3;
#pragma unroll
            for (int off = 4; off <= 16; off <<= 1) {
                mx0 = fmaxf(mx0, __shfl_xor_sync(0xffffffffu, mx0, off));
                mx1 = fmaxf(mx1, __shfl_xor_sync(0xffffffffu, mx1, off));
                mn0 = fminf(mn0, __shfl_xor_sync(0xffffffffu, mn0, off));
                mn1 = fminf(mn1, __shfl_xor_sync(0xffffffffu, mn1, off));
                sm0 += __shfl_xor_sync(0xffffffffu, sm0, off);
                sm1 += __shfl_xor_sync(0xffffffffu, sm1, off);
                sq0 += __shfl_xor_sync(0xffffffffu, sq0, off);
                sq1 += __shfl_xor_sync(0xffffffffu, sq1, off);
            }
            if (lane < 4) {
                size_t o = (size_t)node * HDIM + col;
                g_aggmax[st][o]     = mx0;
                g_aggmax[st][o + 1] = mx1;
                g_aggmin[st][o]     = mn0;
                g_aggmin[st][o + 1] = mn1;
                atomicAdd(&s_sum[col], sm0);  atomicAdd(&s_sum[col + 1], sm1);
                atomicAdd(&s_sq[col],  sq0);  atomicAdd(&s_sq[col + 1],  sq1);
            }
        }
    }
    __syncthreads();
    if (tid < 128) {
        atomicAdd(&g_bn2_sum[st][tid], s_sum[tid]);
        atomicAdd(&g_bn2_sq[st][tid], s_sq[tid]);
    }
}

// ---------------------------------------------------------------------------
// 8: final GEMM
// ---------------------------------------------------------------------------
__global__ __launch_bounds__(256) void k_final(const float* __restrict__ fW, const float* __restrict__ fb) {
    __shared__ float Fs[32][LDW];
    __shared__ float Ws[32][LDW];
    __shared__ float s_sum[HDIM], s_sq[HDIM];
    const int n0 = blockIdx.x * 128;
    const int tid = threadIdx.x, ty = tid >> 4, tx = tid & 15;
    if (tid < 128) { s_sum[tid] = 0.f; s_sq[tid] = 0.f; }
    ull acc[8][4];
#pragma unroll
    for (int i = 0; i < 8; i++)
#pragma unroll
        for (int j = 0; j < 4; j++) acc[i][j] = 0ull;

    for (int kc = 0; kc < 2 * HDIM; kc += 32) {
        __syncthreads();
        for (int idx = tid; idx < 128 * 32; idx += 256) {
            int nl = idx >> 5, kk = idx & 31;
            int kf = kc + kk;
            int st = kf >> 7, ch = kf & 127;
            float a2 = g_a2[st][ch], c2 = g_c2[st][ch];
            size_t o = (size_t)(n0 + nl) * HDIM + ch;
            float v = (a2 >= 0.f) ? g_aggmax[st][o] : g_aggmin[st][o];
            Fs[kk][nl] = fmaxf(fmaf(a2, v, c2), 0.f);
        }
        for (int idx = tid; idx < 32 * HDIM; idx += 256) {
            int kk = idx >> 7, col = idx & 127;
            Ws[kk][col] = fW[(size_t)(kc + kk) * HDIM + col];
        }
        __syncthreads();
#pragma unroll 8
        for (int kk = 0; kk < 32; kk++)
            micro_step(&Fs[kk][0], &Ws[kk][0], ty * 8, tx * 8, acc);
    }
    float outv[8][8];
    unpack_acc(acc, outv);
    float bj[8];
#pragma unroll
    for (int j = 0; j < 8; j++) bj[j] = fb[tx * 8 + j];
#pragma unroll
    for (int i = 0; i < 8; i++)
#pragma unroll
        for (int j = 0; j < 8; j++) outv[i][j] += bj[j];
#pragma unroll
    for (int i = 0; i < 8; i++) {
        size_t row = (size_t)(n0 + ty * 8 + i) * HDIM + tx * 8;
        *(float4*)&g_hF[row]     = make_float4(outv[i][0], outv[i][1], outv[i][2], outv[i][3]);
        *(float4*)&g_hF[row + 4] = make_float4(outv[i][4], outv[i][5], outv[i][6], outv[i][7]);
    }
#pragma unroll
    for (int j = 0; j < 8; j++) {
        float cs = 0.f, cq = 0.f;
#pragma unroll
        for (int i = 0; i < 8; i++) { float v = outv[i][j]; cs += v; cq += v * v; }
        cs += __shfl_xor_sync(0xffffffffu, cs, 16);
        cq += __shfl_xor_sync(0xffffffffu, cq, 16);
        if ((ty & 1) == 0) {
            int col = tx * 8 + j;
            atomicAdd(&s_sum[col], cs);
            atomicAdd(&s_sq[col], cq);
        }
    }
    __syncthreads();
    if (tid < 128) {
        atomicAdd(&g_bnF_sum[tid], s_sum[tid]);
        atomicAdd(&g_bnF_sq[tid], s_sq[tid]);
    }
}

// ---------------------------------------------------------------------------
// 9: output elementwise
// ---------------------------------------------------------------------------
__global__ void k_out(float* __restrict__ out) {
    int idx = blockIdx.x * 256 + threadIdx.x;
    int col = idx & 127;
    out[idx] = fmaxf(fmaf(g_aF[col], g_hF[idx], g_cF[col]), 0.f);
}

// ---------------------------------------------------------------------------
// launcher
// ---------------------------------------------------------------------------
extern "C" void kernel_launch(void* const* d_in, const int* in_sizes, int n_in,
                              void* d_out, int out_size) {
    (void)in_sizes; (void)n_in; (void)out_size;
    const float* x     = (const float*)d_in[0];
    const float* s_W1  = (const float*)d_in[2];
    const float* s_b1  = (const float*)d_in[3];
    const float* s_g1  = (const float*)d_in[4];
    const float* s_be1 = (const float*)d_in[5];
    const float* s_W2  = (const float*)d_in[6];
    const float* s_b2  = (const float*)d_in[7];
    const float* s_g2  = (const float*)d_in[8];
    const float* s_be2 = (const float*)d_in[9];
    const float* t_W1  = (const float*)d_in[10];
    const float* t_b1  = (const float*)d_in[11];
    const float* t_g1  = (const float*)d_in[12];
    const float* t_be1 = (const float*)d_in[13];
    const float* t_W2  = (const float*)d_in[14];
    const float* t_b2  = (const float*)d_in[15];
    const float* t_g2  = (const float*)d_in[16];
    const float* t_be2 = (const float*)d_in[17];
    const float* f_W   = (const float*)d_in[18];
    const float* f_b   = (const float*)d_in[19];
    const float* f_g   = (const float*)d_in[20];
    const float* f_be  = (const float*)d_in[21];
    float* out = (float*)d_out;

    const float invE  = 1.f / (float)EDGES;
    const float invNT = 1.f / (float)NT;

    cudaFuncSetAttribute(k_edge_mma, cudaFuncAttributeMaxDynamicSharedMemorySize, EDGE_SMEM);
    cudaFuncSetAttribute(k_d2_mma,   cudaFuncAttributeMaxDynamicSharedMemorySize, D2_SMEM);

    k_zero<<<1, 128>>>();
    k_sq<<<NT / 8, 256>>>(x);
    k_d2_mma<<<dim3(NNODE / 128, NNODE / 128, BBATCH), 256, D2_SMEM>>>(x);
    k_topk<<<NT / TKW, 32 * TKW>>>();
    k_pq<<<dim3(NT / 128, 1, 4), 256>>>(x, s_W1, s_b1, t_W1, t_b1);
    k_bn1stats<<<NT / 32, 128>>>();
    k_bnfin<<<1, 128>>>(0, 0, s_g1, s_be1, invE);
    k_bnfin<<<1, 128>>>(0, 1, t_g1, t_be1, invE);
    k_w2prep<<<2, 256>>>(s_W2, t_W2);
    k_edge_mma<<<dim3(NT / 8, 1, 2), 256, EDGE_SMEM>>>(s_b2, t_b2);
    k_bnfin<<<1, 128>>>(1, 0, s_g2, s_be2, invE);
    k_bnfin<<<1, 128>>>(1, 1, t_g2, t_be2, invE);
    k_final<<<NT / 128, 256>>>(f_W, f_b);
    k_bnfin<<<1, 128>>>(2, 0, f_g, f_be, invNT);
    k_out<<<(NT * HDIM) / 256, 256>>>(out);
}

// round 16
// speedup vs baseline: 1.5876x; 1.0247x over previous
#include <cuda_runtime.h>
#include <cuda_bf16.h>
#include <cstdint>

#define BBATCH 16
#define NNODE  2048
#define CDIM   64
#define HDIM   128
#define KNEIGH 16
#define NT     (BBATCH*NNODE)        /* 32768 nodes  */
#define EDGES  (NT*KNEIGH)           /* 524288 edges */
#define BN_EPS 1e-5f
#define LDW    132                   /* smem tile pitch (floats) for FFMA GEMMs */
#define TKW    4                     /* top-k: rows (warps) per block */
#define BKP    136                   /* bf16 tile pitch (elements) for edge mma tiles */
#define W2T_BYTES (HDIM*BKP*2)       /* 34816 bytes per hi/lo tile */
#define EDGE_SMEM (4*W2T_BYTES)      /* 139264 */

typedef unsigned long long ull;

// ---------------------------------------------------------------------------
// Static device scratch (no runtime allocation allowed)
// ---------------------------------------------------------------------------
__device__ float g_sq[NT];
__device__ float g_d2[(size_t)BBATCH * NNODE * NNODE];        // 256 MB
__device__ int   g_idx[EDGES];
__device__ __align__(16) float g_p[2][(size_t)NT * HDIM];
__device__ __align__(16) float g_q[2][(size_t)NT * HDIM];
__device__ float g_bn1_sum[2][HDIM], g_bn1_sq[2][HDIM];
__device__ __align__(16) float g_a1[2][HDIM], g_c1[2][HDIM];
__device__ __align__(16) float g_aggmax[2][(size_t)NT * HDIM];
__device__ __align__(16) float g_aggmin[2][(size_t)NT * HDIM];
__device__ float g_bn2_sum[2][HDIM], g_bn2_sq[2][HDIM];
__device__ float g_a2[2][HDIM], g_c2[2][HDIM];
__device__ __align__(16) float g_hF[(size_t)NT * HDIM];
__device__ float g_bnF_sum[HDIM], g_bnF_sq[HDIM];
__device__ float g_aF[HDIM], g_cF[HDIM];
// W2^T split into bf16 hi/lo, row-major [n][k] with pitch BKP (raw smem image)
__device__ __align__(16) unsigned char g_w2t_hi[2][W2T_BYTES];
__device__ __align__(16) unsigned char g_w2t_lo[2][W2T_BYTES];

// ---------------------------------------------------------------------------
// f32x2 packed-FMA helpers
// ---------------------------------------------------------------------------
__device__ __forceinline__ ull pk2(float lo, float hi) {
    ull r; asm("mov.b64 %0, {%1, %2};" : "=l"(r) : "f"(lo), "f"(hi)); return r;
}
__device__ __forceinline__ void fma2(ull &d, ull a, ull b) {
    asm("fma.rn.f32x2 %0, %1, %2, %0;" : "+l"(d) : "l"(a), "l"(b));
}
__device__ __forceinline__ float2 up2(ull v) {
    float2 f; asm("mov.b64 {%0, %1}, %2;" : "=f"(f.x), "=f"(f.y) : "l"(v)); return f;
}

__device__ __forceinline__ void micro_step(const float* __restrict__ Arow,
                                           const float* __restrict__ Brow,
                                           int ty8, int tx8, ull acc[8][4]) {
    float4 a0 = *(const float4*)(Arow + ty8);
    float4 a1 = *(const float4*)(Arow + ty8 + 4);
    float4 b0 = *(const float4*)(Brow + tx8);
    float4 b1 = *(const float4*)(Brow + tx8 + 4);
    ull bv0 = pk2(b0.x, b0.y), bv1 = pk2(b0.z, b0.w);
    ull bv2 = pk2(b1.x, b1.y), bv3 = pk2(b1.z, b1.w);
    float av[8] = {a0.x, a0.y, a0.z, a0.w, a1.x, a1.y, a1.z, a1.w};
#pragma unroll
    for (int i = 0; i < 8; i++) {
        ull ai = pk2(av[i], av[i]);
        fma2(acc[i][0], ai, bv0);
        fma2(acc[i][1], ai, bv1);
        fma2(acc[i][2], ai, bv2);
        fma2(acc[i][3], ai, bv3);
    }
}

__device__ __forceinline__ void unpack_acc(ull acc[8][4], float outv[8][8]) {
#pragma unroll
    for (int i = 0; i < 8; i++)
#pragma unroll
        for (int j2 = 0; j2 < 4; j2++) {
            float2 u = up2(acc[i][j2]);
            outv[i][2*j2]   = u.x;
            outv[i][2*j2+1] = u.y;
        }
}

// mma.sync bf16 (sm_80 baseline feature)
__device__ __forceinline__ void mma16816(float* d, const uint32_t* a, const uint32_t* b) {
    asm volatile(
        "mma.sync.aligned.m16n8k16.row.col.f32.bf16.bf16.f32 "
        "{%0,%1,%2,%3}, {%4,%5,%6,%7}, {%8,%9}, {%0,%1,%2,%3};"
        : "+f"(d[0]), "+f"(d[1]), "+f"(d[2]), "+f"(d[3])
        : "r"(a[0]), "r"(a[1]), "r"(a[2]), "r"(a[3]), "r"(b[0]), "r"(b[1]));
}

// split a float into bf16 hi/lo pair packed as __nv_bfloat162 stores
__device__ __forceinline__ void split2(float z0, float z1,
                                       __nv_bfloat162 &hi, __nv_bfloat162 &lo) {
    __nv_bfloat16 h0 = __float2bfloat16_rn(z0), h1 = __float2bfloat16_rn(z1);
    hi.x = h0; hi.y = h1;
    lo.x = __float2bfloat16_rn(z0 - __bfloat162float(h0));
    lo.y = __float2bfloat16_rn(z1 - __bfloat162float(h1));
}

// ---------------------------------------------------------------------------
// 0: zero accumulators
// ---------------------------------------------------------------------------
__global__ void k_zero() {
    int t = threadIdx.x;
    if (t < HDIM) {
        g_bn1_sum[0][t] = 0.f; g_bn1_sum[1][t] = 0.f;
        g_bn1_sq[0][t]  = 0.f; g_bn1_sq[1][t]  = 0.f;
        g_bn2_sum[0][t] = 0.f; g_bn2_sum[1][t] = 0.f;
        g_bn2_sq[0][t]  = 0.f; g_bn2_sq[1][t]  = 0.f;
        g_bnF_sum[t]    = 0.f; g_bnF_sq[t]     = 0.f;
    }
}

// ---------------------------------------------------------------------------
// 1: per-node squared norms
// ---------------------------------------------------------------------------
__global__ void k_sq(const float* __restrict__ x) {
    int w    = (blockIdx.x * blockDim.x + threadIdx.x) >> 5;
    int lane = threadIdx.x & 31;
    if (w >= NT) return;
    float v0 = x[(size_t)w * CDIM + lane];
    float v1 = x[(size_t)w * CDIM + 32 + lane];
    float s = v0 * v0 + v1 * v1;
#pragma unroll
    for (int off = 16; off; off >>= 1) s += __shfl_xor_sync(0xffffffffu, s, off);
    if (lane == 0) g_sq[w] = s;
}

// ---------------------------------------------------------------------------
// 2: pairwise squared distances per batch (exact fp32 FFMA — kNN selection
//    needs full fp32 d2; reduced-precision variants flip neighbors)
// ---------------------------------------------------------------------------
__global__ __launch_bounds__(256) void k_d2(const float* __restrict__ x) {
    __shared__ float Ai[32][LDW];
    __shared__ float Aj[32][LDW];
    const int b  = blockIdx.z;
    const int i0 = blockIdx.y * 128, j0 = blockIdx.x * 128;
    const float* X = x + (size_t)b * NNODE * CDIM;
    const int tid = threadIdx.x, ty = tid >> 4, tx = tid & 15;
    ull acc[8][4];
#pragma unroll
    for (int i = 0; i < 8; i++)
#pragma unroll
        for (int j = 0; j < 4; j++) acc[i][j] = 0ull;

    for (int kc = 0; kc < CDIM; kc += 32) {
        __syncthreads();
        for (int idx = tid; idx < 128 * 32; idx += 256) {
            int row = idx >> 5, kk = idx & 31;
            Ai[kk][row] = X[(size_t)(i0 + row) * CDIM + kc + kk];
            Aj[kk][row] = X[(size_t)(j0 + row) * CDIM + kc + kk];
        }
        __syncthreads();
#pragma unroll 8
        for (int kk = 0; kk < 32; kk++)
            micro_step(&Ai[kk][0], &Aj[kk][0], ty * 8, tx * 8, acc);
    }
    float outv[8][8];
    unpack_acc(acc, outv);
    float sqi[8], sqj[8];
#pragma unroll
    for (int i = 0; i < 8; i++) sqi[i] = g_sq[b * NNODE + i0 + ty * 8 + i];
#pragma unroll
    for (int j = 0; j < 8; j++) sqj[j] = g_sq[b * NNODE + j0 + tx * 8 + j];
#pragma unroll
    for (int i = 0; i < 8; i++) {
        size_t row = ((size_t)(b * NNODE + i0 + ty * 8 + i)) * NNODE + j0 + tx * 8;
        float v[8];
#pragma unroll
        for (int j = 0; j < 8; j++) v[j] = sqi[i] + sqj[j] - 2.f * outv[i][j];
        *(float4*)&g_d2[row]     = make_float4(v[0], v[1], v[2], v[3]);
        *(float4*)&g_d2[row + 4] = make_float4(v[4], v[5], v[6], v[7]);
    }
}

// ---------------------------------------------------------------------------
// 3: top-K smallest per row (warp per row) with per-lane top-2 cache.
//    Winner pops its cached 2nd-min instead of rescanning; rescans only when
//    a lane's cache is exhausted (expected ~3-4x per row instead of 16x).
// ---------------------------------------------------------------------------
__global__ __launch_bounds__(32 * TKW) void k_topk() {
    __shared__ float vals[TKW][NNODE];
    const int warp = threadIdx.x >> 5, lane = threadIdx.x & 31;
    const int row  = blockIdx.x * TKW + warp;
    const size_t rowoff = (size_t)row * NNODE;
    const int b = row >> 11;
    float* v = vals[warp];

    // fused load + per-lane top-2 scan (scan order => i1 < i2 among ties)
    float m1 = 3.0e38f, m2 = 3.0e38f;
    int   i1 = 0x7fffffff, i2 = 0x7fffffff;
#pragma unroll 8
    for (int j = lane; j < NNODE; j += 32) {
        float x = g_d2[rowoff + j];
        v[j] = x;
        if (x < m1)      { m2 = m1; i2 = i1; m1 = x; i1 = j; }
        else if (x < m2) { m2 = x; i2 = j; }
    }
    __syncwarp();

    for (int k = 0; k < KNEIGH; k++) {
        // warp argmin over lane minima (value, then smaller index)
        float wv = m1; int wi = i1;
#pragma unroll
        for (int off = 16; off; off >>= 1) {
            float ov = __shfl_xor_sync(0xffffffffu, wv, off);
            int   oi = __shfl_xor_sync(0xffffffffu, wi, off);
            if (ov < wv || (ov == wv && oi < wi)) { wv = ov; wi = oi; }
        }
        if (lane == 0) g_idx[(size_t)row * KNEIGH + k] = b * NNODE + wi;
        if ((wi & 31) == lane) {
            v[wi] = 3.0e38f;
            if (i2 != 0x7fffffff) {
                // pop cached second-min
                m1 = m2; i1 = i2;
                m2 = 3.0e38f; i2 = 0x7fffffff;
            } else {
                // cache exhausted: rescan own 64 entries (removed == +INF)
                m1 = 3.0e38f; m2 = 3.0e38f; i1 = 0x7fffffff; i2 = 0x7fffffff;
#pragma unroll 8
                for (int j = lane; j < NNODE; j += 32) {
                    float x = v[j];
                    if (x < m1)      { m2 = m1; i2 = i1; m1 = x; i1 = j; }
                    else if (x < m2) { m2 = x; i2 = j; }
                }
            }
        }
        __syncwarp();
    }
}

// ---------------------------------------------------------------------------
// 4: p/q GEMMs
// ---------------------------------------------------------------------------
__global__ __launch_bounds__(256) void k_pq(const float* __restrict__ x,
                                            const float* __restrict__ sW1, const float* __restrict__ sb1,
                                            const float* __restrict__ tW1, const float* __restrict__ tb1) {
    __shared__ float Xs[32][LDW];
    __shared__ float Ws[32][LDW];
    const int z   = blockIdx.z;
    const int st  = z >> 1;
    const bool isP = (z & 1) == 0;
    const float* W1 = st ? tW1 : sW1;
    const float* B1 = st ? tb1 : sb1;
    const int n0 = blockIdx.x * 128;
    const int tid = threadIdx.x, ty = tid >> 4, tx = tid & 15;
    ull acc[8][4];
#pragma unroll
    for (int i = 0; i < 8; i++)
#pragma unroll
        for (int j = 0; j < 4; j++) acc[i][j] = 0ull;

    for (int kc = 0; kc < CDIM; kc += 32) {
        __syncthreads();
        for (int idx = tid; idx < 128 * 32; idx += 256) {
            int r = idx >> 5, kk = idx & 31;
            Xs[kk][r] = x[(size_t)(n0 + r) * CDIM + kc + kk];
        }
        for (int idx = tid; idx < 32 * HDIM; idx += 256) {
            int kk = idx >> 7, col = idx & 127;
            int kr = kc + kk;
            float w = W1[(size_t)(CDIM + kr) * HDIM + col];
            if (isP) w = W1[(size_t)kr * HDIM + col] - w;
            Ws[kk][col] = w;
        }
        __syncthreads();
#pragma unroll 8
        for (int kk = 0; kk < 32; kk++)
            micro_step(&Xs[kk][0], &Ws[kk][0], ty * 8, tx * 8, acc);
    }
    float outv[8][8];
    unpack_acc(acc, outv);
    float* O = isP ? g_p[st] : g_q[st];
    float bj[8];
#pragma unroll
    for (int j = 0; j < 8; j++) bj[j] = isP ? B1[tx * 8 + j] : 0.f;
#pragma unroll
    for (int i = 0; i < 8; i++) {
        size_t row = (size_t)(n0 + ty * 8 + i) * HDIM + tx * 8;
        *(float4*)&O[row]     = make_float4(outv[i][0] + bj[0], outv[i][1] + bj[1],
                                            outv[i][2] + bj[2], outv[i][3] + bj[3]);
        *(float4*)&O[row + 4] = make_float4(outv[i][4] + bj[4], outv[i][5] + bj[5],
                                            outv[i][6] + bj[6], outv[i][7] + bj[7]);
    }
}

// ---------------------------------------------------------------------------
// 5: BN1 statistics
// ---------------------------------------------------------------------------
__global__ void k_bn1stats() {
    const int h = threadIdx.x;
    const int node0 = blockIdx.x * 32;
    float s0 = 0.f, q0 = 0.f, s1 = 0.f, q1 = 0.f;
    for (int nl = 0; nl < 32; nl++) {
        int n = node0 + nl;
        float p0 = g_p[0][(size_t)n * HDIM + h];
        float p1 = g_p[1][(size_t)n * HDIM + h];
        for (int k = 0; k < KNEIGH; k++) {
            int j = g_idx[(size_t)n * KNEIGH + k];
            float a = p0 + g_q[0][(size_t)j * HDIM + h];
            float b = p1 + g_q[1][(size_t)j * HDIM + h];
            s0 += a; q0 += a * a;
            s1 += b; q1 += b * b;
        }
    }
    atomicAdd(&g_bn1_sum[0][h], s0); atomicAdd(&g_bn1_sq[0][h], q0);
    atomicAdd(&g_bn1_sum[1][h], s1); atomicAdd(&g_bn1_sq[1][h], q1);
}

// ---------------------------------------------------------------------------
// 6: BN finalize
// ---------------------------------------------------------------------------
__global__ void k_bnfin(int which, int st, const float* __restrict__ g,
                        const float* __restrict__ be, float invN) {
    int h = threadIdx.x;
    float s, q;
    if (which == 0)      { s = g_bn1_sum[st][h]; q = g_bn1_sq[st][h]; }
    else if (which == 1) { s = g_bn2_sum[st][h]; q = g_bn2_sq[st][h]; }
    else                 { s = g_bnF_sum[h];     q = g_bnF_sq[h]; }
    float m   = s * invN;
    float var = fmaxf(q * invN - m * m, 0.f);
    float a   = g[h] * rsqrtf(var + BN_EPS);
    float c   = be[h] - m * a;
    if (which == 0)      { g_a1[st][h] = a; g_c1[st][h] = c; }
    else if (which == 1) { g_a2[st][h] = a; g_c2[st][h] = c; }
    else                 { g_aF[h] = a;     g_cF[h] = c; }
}

// ---------------------------------------------------------------------------
// 6b: prep W2^T split bf16 hi/lo, row-major [n][k] pitch BKP (raw smem image)
// ---------------------------------------------------------------------------
__global__ void k_w2prep(const float* __restrict__ sW2, const float* __restrict__ tW2) {
    const int st = blockIdx.x;
    const float* W2 = st ? tW2 : sW2;
    __nv_bfloat16* H = (__nv_bfloat16*)g_w2t_hi[st];
    __nv_bfloat16* L = (__nv_bfloat16*)g_w2t_lo[st];
    for (int lin = threadIdx.x; lin < HDIM * HDIM; lin += blockDim.x) {
        int n = lin & 127, k = lin >> 7;
        float w = W2[(size_t)k * HDIM + n];
        __nv_bfloat16 hi = __float2bfloat16_rn(w);
        __nv_bfloat16 lo = __float2bfloat16_rn(w - __bfloat162float(hi));
        H[n * BKP + k] = hi;
        L[n * BKP + k] = lo;
    }
}

// ---------------------------------------------------------------------------
// 7: edge GEMM on mma.sync bf16 (split hi/lo, 3 passes)
// ---------------------------------------------------------------------------
__global__ __launch_bounds__(256)
void k_edge_mma(const float* __restrict__ sb2v, const float* __restrict__ tb2v) {
    extern __shared__ __nv_bfloat16 dsm[];
    __shared__ int   sidx[128];
    __shared__ float s_sum[128], s_sq[128], b2s[128];

    const int st = blockIdx.z;
    const int node0 = blockIdx.x * 8;
    const int tid = threadIdx.x;
    const int wid = tid >> 5, lane = tid & 31;
    const int warp_m = wid & 3, warp_n = wid >> 2;
    const float* B2 = st ? tb2v : sb2v;
    const float* P  = g_p[st];
    const float* Q  = g_q[st];
    const float* A1 = g_a1[st];
    const float* C1 = g_c1[st];

    __nv_bfloat16* Ahi = dsm;
    __nv_bfloat16* Alo = Ahi + HDIM * BKP;
    __nv_bfloat16* Bhi = Alo + HDIM * BKP;
    __nv_bfloat16* Blo = Bhi + HDIM * BKP;

    if (tid < 128) {
        sidx[tid]  = g_idx[(size_t)node0 * KNEIGH + tid];
        s_sum[tid] = 0.f; s_sq[tid] = 0.f;
        b2s[tid]   = B2[tid];
    }

    {
        const uint4* srch = (const uint4*)g_w2t_hi[st];
        const uint4* srcl = (const uint4*)g_w2t_lo[st];
        uint4* dsth = (uint4*)Bhi;
        uint4* dstl = (uint4*)Blo;
        for (int i = tid; i < W2T_BYTES / 16; i += 256) { dsth[i] = srch[i]; dstl[i] = srcl[i]; }
    }

    {
        int e = tid >> 1, half = tid & 1, k0 = half * 64;
        int n = node0 + (e >> 4);
        int j = sidx[e];
        const float4* Pr = (const float4*)(P + (size_t)n * HDIM + k0);
        const float4* Qr = (const float4*)(Q + (size_t)j * HDIM + k0);
        const float4* Av = (const float4*)(A1 + k0);
        const float4* Cv = (const float4*)(C1 + k0);
        __nv_bfloat16* ah = Ahi + e * BKP + k0;
        __nv_bfloat16* al = Alo + e * BKP + k0;
#pragma unroll
        for (int i = 0; i < 16; i++) {
            float4 pv = Pr[i], qv = Qr[i], av = Av[i], cv = Cv[i];
            float z0 = fmaxf(fmaf(av.x, pv.x + qv.x, cv.x), 0.f);
            float z1 = fmaxf(fmaf(av.y, pv.y + qv.y, cv.y), 0.f);
            float z2 = fmaxf(fmaf(av.z, pv.z + qv.z, cv.z), 0.f);
            float z3 = fmaxf(fmaf(av.w, pv.w + qv.w, cv.w), 0.f);
            __nv_bfloat162 h0, l0, h1, l1;
            split2(z0, z1, h0, l0); split2(z2, z3, h1, l1);
            *(__nv_bfloat162*)(ah + i * 4)     = h0;
            *(__nv_bfloat162*)(ah + i * 4 + 2) = h1;
            *(__nv_bfloat162*)(al + i * 4)     = l0;
            *(__nv_bfloat162*)(al + i * 4 + 2) = l1;
        }
    }
    __syncthreads();

    float acc[2][8][4];
#pragma unroll
    for (int mt = 0; mt < 2; mt++)
#pragma unroll
        for (int nt = 0; nt < 8; nt++)
#pragma unroll
            for (int r = 0; r < 4; r++) acc[mt][nt][r] = 0.f;

    const int arow = warp_m * 32 + (lane >> 2);
    const int acol = (lane & 3) * 2;
    const int brow = warp_n * 64 + (lane >> 2);

#pragma unroll
    for (int pass = 0; pass < 3; pass++) {
        const __nv_bfloat16* As = (pass == 2) ? Alo : Ahi;
        const __nv_bfloat16* Bs = (pass == 1) ? Blo : Bhi;
#pragma unroll
        for (int k8 = 0; k8 < 8; k8++) {
            int kk = k8 * 16 + acol;
            uint32_t afr[2][4];
#pragma unroll
            for (int mt = 0; mt < 2; mt++) {
                const __nv_bfloat16* ap = As + (size_t)(arow + mt * 16) * BKP + kk;
                afr[mt][0] = *(const uint32_t*)(ap);
                afr[mt][1] = *(const uint32_t*)(ap + 8 * BKP);
                afr[mt][2] = *(const uint32_t*)(ap + 8);
                afr[mt][3] = *(const uint32_t*)(ap + 8 * BKP + 8);
            }
            uint32_t bfr[8][2];
#pragma unroll
            for (int nt = 0; nt < 8; nt++) {
                const __nv_bfloat16* bp = Bs + (size_t)(brow + nt * 8) * BKP + kk;
                bfr[nt][0] = *(const uint32_t*)(bp);
                bfr[nt][1] = *(const uint32_t*)(bp + 8);
            }
#pragma unroll
            for (int mt = 0; mt < 2; mt++)
#pragma unroll
                for (int nt = 0; nt < 8; nt++)
                    mma16816(acc[mt][nt], afr[mt], bfr[nt]);
        }
    }

#pragma unroll
    for (int mt = 0; mt < 2; mt++) {
        const int node = node0 + warp_m * 2 + mt;
#pragma unroll
        for (int nt = 0; nt < 8; nt++) {
            const int col = warp_n * 64 + nt * 8 + (lane & 3) * 2;
            float bb0 = b2s[col], bb1 = b2s[col + 1];
            float v0 = acc[mt][nt][0] + bb0, v1 = acc[mt][nt][1] + bb1;
            float v2 = acc[mt][nt][2] + bb0, v3 = acc[mt][nt][3] + bb1;
            float mx0 = fmaxf(v0, v2), mx1 = fmaxf(v1, v3);
            float mn0 = fminf(v0, v2), mn1 = fminf(v1, v3);
            float sm0 = v0 + v2,       sm1 = v1 + v3;
            float sq0 = v0 * v0 + v2 * v2, sq1 = v1 * v1 + v3 * v3;
#pragma unroll
            for (int off = 4; off <= 16; off <<= 1) {
                mx0 = fmaxf(mx0, __shfl_xor_sync(0xffffffffu, mx0, off));
                mx1 = fmaxf(mx1, __shfl_xor_sync(0xffffffffu, mx1, off));
                mn0 = fminf(mn0, __shfl_xor_sync(0xffffffffu, mn0, off));
                mn1 = fminf(mn1, __shfl_xor_sync(0xffffffffu, mn1, off));
                sm0 += __shfl_xor_sync(0xffffffffu, sm0, off);
                sm1 += __shfl_xor_sync(0xffffffffu, sm1, off);
                sq0 += __shfl_xor_sync(0xffffffffu, sq0, off);
                sq1 += __shfl_xor_sync(0xffffffffu, sq1, off);
            }
            if (lane < 4) {
                size_t o = (size_t)node * HDIM + col;
                g_aggmax[st][o]     = mx0;
                g_aggmax[st][o + 1] = mx1;
                g_aggmin[st][o]     = mn0;
                g_aggmin[st][o + 1] = mn1;
                atomicAdd(&s_sum[col], sm0);  atomicAdd(&s_sum[col + 1], sm1);
                atomicAdd(&s_sq[col],  sq0);  atomicAdd(&s_sq[col + 1],  sq1);
            }
        }
    }
    __syncthreads();
    if (tid < 128) {
        atomicAdd(&g_bn2_sum[st][tid], s_sum[tid]);
        atomicAdd(&g_bn2_sq[st][tid], s_sq[tid]);
    }
}

// ---------------------------------------------------------------------------
// 8: final GEMM
// ---------------------------------------------------------------------------
__global__ __launch_bounds__(256) void k_final(const float* __restrict__ fW, const float* __restrict__ fb) {
    __shared__ float Fs[32][LDW];
    __shared__ float Ws[32][LDW];
    __shared__ float s_sum[HDIM], s_sq[HDIM];
    const int n0 = blockIdx.x * 128;
    const int tid = threadIdx.x, ty = tid >> 4, tx = tid & 15;
    if (tid < 128) { s_sum[tid] = 0.f; s_sq[tid] = 0.f; }
    ull acc[8][4];
#pragma unroll
    for (int i = 0; i < 8; i++)
#pragma unroll
        for (int j = 0; j < 4; j++) acc[i][j] = 0ull;

    for (int kc = 0; kc < 2 * HDIM; kc += 32) {
        __syncthreads();
        for (int idx = tid; idx < 128 * 32; idx += 256) {
            int nl = idx >> 5, kk = idx & 31;
            int kf = kc + kk;
            int st = kf >> 7, ch = kf & 127;
            float a2 = g_a2[st][ch], c2 = g_c2[st][ch];
            size_t o = (size_t)(n0 + nl) * HDIM + ch;
            float v = (a2 >= 0.f) ? g_aggmax[st][o] : g_aggmin[st][o];
            Fs[kk][nl] = fmaxf(fmaf(a2, v, c2), 0.f);
        }
        for (int idx = tid; idx < 32 * HDIM; idx += 256) {
            int kk = idx >> 7, col = idx & 127;
            Ws[kk][col] = fW[(size_t)(kc + kk) * HDIM + col];
        }
        __syncthreads();
#pragma unroll 8
        for (int kk = 0; kk < 32; kk++)
            micro_step(&Fs[kk][0], &Ws[kk][0], ty * 8, tx * 8, acc);
    }
    float outv[8][8];
    unpack_acc(acc, outv);
    float bj[8];
#pragma unroll
    for (int j = 0; j < 8; j++) bj[j] = fb[tx * 8 + j];
#pragma unroll
    for (int i = 0; i < 8; i++)
#pragma unroll
        for (int j = 0; j < 8; j++) outv[i][j] += bj[j];
#pragma unroll
    for (int i = 0; i < 8; i++) {
        size_t row = (size_t)(n0 + ty * 8 + i) * HDIM + tx * 8;
        *(float4*)&g_hF[row]     = make_float4(outv[i][0], outv[i][1], outv[i][2], outv[i][3]);
        *(float4*)&g_hF[row + 4] = make_float4(outv[i][4], outv[i][5], outv[i][6], outv[i][7]);
    }
#pragma unroll
    for (int j = 0; j < 8; j++) {
        float cs = 0.f, cq = 0.f;
#pragma unroll
        for (int i = 0; i < 8; i++) { float v = outv[i][j]; cs += v; cq += v * v; }
        cs += __shfl_xor_sync(0xffffffffu, cs, 16);
        cq += __shfl_xor_sync(0xffffffffu, cq, 16);
        if ((ty & 1) == 0) {
            int col = tx * 8 + j;
            atomicAdd(&s_sum[col], cs);
            atomicAdd(&s_sq[col], cq);
        }
    }
    __syncthreads();
    if (tid < 128) {
        atomicAdd(&g_bnF_sum[tid], s_sum[tid]);
        atomicAdd(&g_bnF_sq[tid], s_sq[tid]);
    }
}

// ---------------------------------------------------------------------------
// 9: output elementwise
// ---------------------------------------------------------------------------
__global__ void k_out(float* __restrict__ out) {
    int idx = blockIdx.x * 256 + threadIdx.x;
    int col = idx & 127;
    out[idx] = fmaxf(fmaf(g_aF[col], g_hF[idx], g_cF[col]), 0.f);
}

// ---------------------------------------------------------------------------
// launcher
// ---------------------------------------------------------------------------
extern "C" void kernel_launch(void* const* d_in, const int* in_sizes, int n_in,
                              void* d_out, int out_size) {
    (void)in_sizes; (void)n_in; (void)out_size;
    const float* x     = (const float*)d_in[0];
    const float* s_W1  = (const float*)d_in[2];
    const float* s_b1  = (const float*)d_in[3];
    const float* s_g1  = (const float*)d_in[4];
    const float* s_be1 = (const float*)d_in[5];
    const float* s_W2  = (const float*)d_in[6];
    const float* s_b2  = (const float*)d_in[7];
    const float* s_g2  = (const float*)d_in[8];
    const float* s_be2 = (const float*)d_in[9];
    const float* t_W1  = (const float*)d_in[10];
    const float* t_b1  = (const float*)d_in[11];
    const float* t_g1  = (const float*)d_in[12];
    const float* t_be1 = (const float*)d_in[13];
    const float* t_W2  = (const float*)d_in[14];
    const float* t_b2  = (const float*)d_in[15];
    const float* t_g2  = (const float*)d_in[16];
    const float* t_be2 = (const float*)d_in[17];
    const float* f_W   = (const float*)d_in[18];
    const float* f_b   = (const float*)d_in[19];
    const float* f_g   = (const float*)d_in[20];
    const float* f_be  = (const float*)d_in[21];
    float* out = (float*)d_out;

    const float invE  = 1.f / (float)EDGES;
    const float invNT = 1.f / (float)NT;

    cudaFuncSetAttribute(k_edge_mma, cudaFuncAttributeMaxDynamicSharedMemorySize, EDGE_SMEM);

    k_zero<<<1, 128>>>();
    k_sq<<<NT / 8, 256>>>(x);
    k_d2<<<dim3(NNODE / 128, NNODE / 128, BBATCH), 256>>>(x);
    k_topk<<<NT / TKW, 32 * TKW>>>();
    k_pq<<<dim3(NT / 128, 1, 4), 256>>>(x, s_W1, s_b1, t_W1, t_b1);
    k_bn1stats<<<NT / 32, 128>>>();
    k_bnfin<<<1, 128>>>(0, 0, s_g1, s_be1, invE);
    k_bnfin<<<1, 128>>>(0, 1, t_g1, t_be1, invE);
    k_w2prep<<<2, 256>>>(s_W2, t_W2);
    k_edge_mma<<<dim3(NT / 8, 1, 2), 256, EDGE_SMEM>>>(s_b2, t_b2);
    k_bnfin<<<1, 128>>>(1, 0, s_g2, s_be2, invE);
    k_bnfin<<<1, 128>>>(1, 1, t_g2, t_be2, invE);
    k_final<<<NT / 128, 256>>>(f_W, f_b);
    k_bnfin<<<1, 128>>>(2, 0, f_g, f_be, invNT);
    k_out<<<(NT * HDIM) / 256, 256>>>(out);
}

// round 17
// speedup vs baseline: 1.6400x; 1.0330x over previous
#include <cuda_runtime.h>
#include <cuda_bf16.h>
#include <cstdint>

#define BBATCH 16
#define NNODE  2048
#define CDIM   64
#define HDIM   128
#define KNEIGH 16
#define NT     (BBATCH*NNODE)        /* 32768 nodes  */
#define EDGES  (NT*KNEIGH)           /* 524288 edges */
#define BN_EPS 1e-5f
#define LDW    132                   /* smem tile pitch (floats) for FFMA GEMMs */
#define TKW    4                     /* top-k: rows (warps) per block */
#define BKP    136                   /* bf16 tile pitch (elements) for edge mma tiles */
#define W2T_BYTES (HDIM*BKP*2)       /* 34816 bytes per hi/lo tile */
#define EDGE_SMEM (4*W2T_BYTES)      /* 139264 */
#define EDGE_BLOCKS 512              /* persistent blocks per stream */
#define EDGE_GROUPS ((NT/8)/EDGE_BLOCKS)  /* 8 node-groups per block */

typedef unsigned long long ull;

// ---------------------------------------------------------------------------
// Static device scratch (no runtime allocation allowed)
// ---------------------------------------------------------------------------
__device__ float g_sq[NT];
__device__ float g_d2[(size_t)BBATCH * NNODE * NNODE];        // 256 MB
__device__ int   g_idx[EDGES];
__device__ __align__(16) float g_p[2][(size_t)NT * HDIM];
__device__ __align__(16) float g_q[2][(size_t)NT * HDIM];
__device__ float g_bn1_sum[2][HDIM], g_bn1_sq[2][HDIM];
__device__ __align__(16) float g_a1[2][HDIM], g_c1[2][HDIM];
__device__ __align__(16) float g_aggmax[2][(size_t)NT * HDIM];
__device__ __align__(16) float g_aggmin[2][(size_t)NT * HDIM];
__device__ float g_bn2_sum[2][HDIM], g_bn2_sq[2][HDIM];
__device__ float g_a2[2][HDIM], g_c2[2][HDIM];
__device__ __align__(16) float g_hF[(size_t)NT * HDIM];
__device__ float g_bnF_sum[HDIM], g_bnF_sq[HDIM];
__device__ float g_aF[HDIM], g_cF[HDIM];
// W2^T split into bf16 hi/lo, row-major [n][k] with pitch BKP (raw smem image)
__device__ __align__(16) unsigned char g_w2t_hi[2][W2T_BYTES];
__device__ __align__(16) unsigned char g_w2t_lo[2][W2T_BYTES];

// ---------------------------------------------------------------------------
// f32x2 packed-FMA helpers
// ---------------------------------------------------------------------------
__device__ __forceinline__ ull pk2(float lo, float hi) {
    ull r; asm("mov.b64 %0, {%1, %2};" : "=l"(r) : "f"(lo), "f"(hi)); return r;
}
__device__ __forceinline__ void fma2(ull &d, ull a, ull b) {
    asm("fma.rn.f32x2 %0, %1, %2, %0;" : "+l"(d) : "l"(a), "l"(b));
}
__device__ __forceinline__ float2 up2(ull v) {
    float2 f; asm("mov.b64 {%0, %1}, %2;" : "=f"(f.x), "=f"(f.y) : "l"(v)); return f;
}

__device__ __forceinline__ void micro_step(const float* __restrict__ Arow,
                                           const float* __restrict__ Brow,
                                           int ty8, int tx8, ull acc[8][4]) {
    float4 a0 = *(const float4*)(Arow + ty8);
    float4 a1 = *(const float4*)(Arow + ty8 + 4);
    float4 b0 = *(const float4*)(Brow + tx8);
    float4 b1 = *(const float4*)(Brow + tx8 + 4);
    ull bv0 = pk2(b0.x, b0.y), bv1 = pk2(b0.z, b0.w);
    ull bv2 = pk2(b1.x, b1.y), bv3 = pk2(b1.z, b1.w);
    float av[8] = {a0.x, a0.y, a0.z, a0.w, a1.x, a1.y, a1.z, a1.w};
#pragma unroll
    for (int i = 0; i < 8; i++) {
        ull ai = pk2(av[i], av[i]);
        fma2(acc[i][0], ai, bv0);
        fma2(acc[i][1], ai, bv1);
        fma2(acc[i][2], ai, bv2);
        fma2(acc[i][3], ai, bv3);
    }
}

__device__ __forceinline__ void unpack_acc(ull acc[8][4], float outv[8][8]) {
#pragma unroll
    for (int i = 0; i < 8; i++)
#pragma unroll
        for (int j2 = 0; j2 < 4; j2++) {
            float2 u = up2(acc[i][j2]);
            outv[i][2*j2]   = u.x;
            outv[i][2*j2+1] = u.y;
        }
}

// mma.sync bf16 (sm_80 baseline feature)
__device__ __forceinline__ void mma16816(float* d, const uint32_t* a, const uint32_t* b) {
    asm volatile(
        "mma.sync.aligned.m16n8k16.row.col.f32.bf16.bf16.f32 "
        "{%0,%1,%2,%3}, {%4,%5,%6,%7}, {%8,%9}, {%0,%1,%2,%3};"
        : "+f"(d[0]), "+f"(d[1]), "+f"(d[2]), "+f"(d[3])
        : "r"(a[0]), "r"(a[1]), "r"(a[2]), "r"(a[3]), "r"(b[0]), "r"(b[1]));
}

// split a float into bf16 hi/lo pair packed as __nv_bfloat162 stores
__device__ __forceinline__ void split2(float z0, float z1,
                                       __nv_bfloat162 &hi, __nv_bfloat162 &lo) {
    __nv_bfloat16 h0 = __float2bfloat16_rn(z0), h1 = __float2bfloat16_rn(z1);
    hi.x = h0; hi.y = h1;
    lo.x = __float2bfloat16_rn(z0 - __bfloat162float(h0));
    lo.y = __float2bfloat16_rn(z1 - __bfloat162float(h1));
}

// ---------------------------------------------------------------------------
// 0: zero accumulators
// ---------------------------------------------------------------------------
__global__ void k_zero() {
    int t = threadIdx.x;
    if (t < HDIM) {
        g_bn1_sum[0][t] = 0.f; g_bn1_sum[1][t] = 0.f;
        g_bn1_sq[0][t]  = 0.f; g_bn1_sq[1][t]  = 0.f;
        g_bn2_sum[0][t] = 0.f; g_bn2_sum[1][t] = 0.f;
        g_bn2_sq[0][t]  = 0.f; g_bn2_sq[1][t]  = 0.f;
        g_bnF_sum[t]    = 0.f; g_bnF_sq[t]     = 0.f;
    }
}

// ---------------------------------------------------------------------------
// 1: per-node squared norms
// ---------------------------------------------------------------------------
__global__ void k_sq(const float* __restrict__ x) {
    int w    = (blockIdx.x * blockDim.x + threadIdx.x) >> 5;
    int lane = threadIdx.x & 31;
    if (w >= NT) return;
    float v0 = x[(size_t)w * CDIM + lane];
    float v1 = x[(size_t)w * CDIM + 32 + lane];
    float s = v0 * v0 + v1 * v1;
#pragma unroll
    for (int off = 16; off; off >>= 1) s += __shfl_xor_sync(0xffffffffu, s, off);
    if (lane == 0) g_sq[w] = s;
}

// ---------------------------------------------------------------------------
// 2: pairwise squared distances per batch (exact fp32 FFMA — kNN selection
//    needs full fp32 d2; reduced-precision variants flip neighbors)
// ---------------------------------------------------------------------------
__global__ __launch_bounds__(256) void k_d2(const float* __restrict__ x) {
    __shared__ float Ai[32][LDW];
    __shared__ float Aj[32][LDW];
    const int b  = blockIdx.z;
    const int i0 = blockIdx.y * 128, j0 = blockIdx.x * 128;
    const float* X = x + (size_t)b * NNODE * CDIM;
    const int tid = threadIdx.x, ty = tid >> 4, tx = tid & 15;
    ull acc[8][4];
#pragma unroll
    for (int i = 0; i < 8; i++)
#pragma unroll
        for (int j = 0; j < 4; j++) acc[i][j] = 0ull;

    for (int kc = 0; kc < CDIM; kc += 32) {
        __syncthreads();
        for (int idx = tid; idx < 128 * 32; idx += 256) {
            int row = idx >> 5, kk = idx & 31;
            Ai[kk][row] = X[(size_t)(i0 + row) * CDIM + kc + kk];
            Aj[kk][row] = X[(size_t)(j0 + row) * CDIM + kc + kk];
        }
        __syncthreads();
#pragma unroll 8
        for (int kk = 0; kk < 32; kk++)
            micro_step(&Ai[kk][0], &Aj[kk][0], ty * 8, tx * 8, acc);
    }
    float outv[8][8];
    unpack_acc(acc, outv);
    float sqi[8], sqj[8];
#pragma unroll
    for (int i = 0; i < 8; i++) sqi[i] = g_sq[b * NNODE + i0 + ty * 8 + i];
#pragma unroll
    for (int j = 0; j < 8; j++) sqj[j] = g_sq[b * NNODE + j0 + tx * 8 + j];
#pragma unroll
    for (int i = 0; i < 8; i++) {
        size_t row = ((size_t)(b * NNODE + i0 + ty * 8 + i)) * NNODE + j0 + tx * 8;
        float v[8];
#pragma unroll
        for (int j = 0; j < 8; j++) v[j] = sqi[i] + sqj[j] - 2.f * outv[i][j];
        *(float4*)&g_d2[row]     = make_float4(v[0], v[1], v[2], v[3]);
        *(float4*)&g_d2[row + 4] = make_float4(v[4], v[5], v[6], v[7]);
    }
}

// ---------------------------------------------------------------------------
// 3: top-K smallest per row (warp per row). Decoupled phases: vectorized
//    float4 row copy (high MLP, DRAM-bound) then smem scan with per-lane
//    top-2 cache; winner pops cached 2nd-min, rescan only on cache underflow.
// ---------------------------------------------------------------------------
__global__ __launch_bounds__(32 * TKW) void k_topk() {
    __shared__ float vals[TKW][NNODE];
    const int warp = threadIdx.x >> 5, lane = threadIdx.x & 31;
    const int row  = blockIdx.x * TKW + warp;
    const size_t rowoff = (size_t)row * NNODE;
    const int b = row >> 11;
    float* v = vals[warp];

    // phase 1: pure vectorized copy — 16 independent 16B loads per lane
    {
        const float4* src = (const float4*)(g_d2 + rowoff);
        float4* dst = (float4*)v;
#pragma unroll
        for (int j4 = lane; j4 < NNODE / 4; j4 += 32) dst[j4] = src[j4];
    }
    __syncwarp();

    // phase 2: per-lane top-2 scan from smem (scan order => i1 < i2 on ties)
    float m1 = 3.0e38f, m2 = 3.0e38f;
    int   i1 = 0x7fffffff, i2 = 0x7fffffff;
#pragma unroll 8
    for (int j = lane; j < NNODE; j += 32) {
        float x = v[j];
        if (x < m1)      { m2 = m1; i2 = i1; m1 = x; i1 = j; }
        else if (x < m2) { m2 = x; i2 = j; }
    }

    for (int k = 0; k < KNEIGH; k++) {
        float wv = m1; int wi = i1;
#pragma unroll
        for (int off = 16; off; off >>= 1) {
            float ov = __shfl_xor_sync(0xffffffffu, wv, off);
            int   oi = __shfl_xor_sync(0xffffffffu, wi, off);
            if (ov < wv || (ov == wv && oi < wi)) { wv = ov; wi = oi; }
        }
        if (lane == 0) g_idx[(size_t)row * KNEIGH + k] = b * NNODE + wi;
        if ((wi & 31) == lane) {
            v[wi] = 3.0e38f;
            if (i2 != 0x7fffffff) {
                m1 = m2; i1 = i2;
                m2 = 3.0e38f; i2 = 0x7fffffff;
            } else {
                m1 = 3.0e38f; m2 = 3.0e38f; i1 = 0x7fffffff; i2 = 0x7fffffff;
#pragma unroll 8
                for (int j = lane; j < NNODE; j += 32) {
                    float x = v[j];
                    if (x < m1)      { m2 = m1; i2 = i1; m1 = x; i1 = j; }
                    else if (x < m2) { m2 = x; i2 = j; }
                }
            }
        }
        __syncwarp();
    }
}

// ---------------------------------------------------------------------------
// 4: p/q GEMMs
// ---------------------------------------------------------------------------
__global__ __launch_bounds__(256) void k_pq(const float* __restrict__ x,
                                            const float* __restrict__ sW1, const float* __restrict__ sb1,
                                            const float* __restrict__ tW1, const float* __restrict__ tb1) {
    __shared__ float Xs[32][LDW];
    __shared__ float Ws[32][LDW];
    const int z   = blockIdx.z;
    const int st  = z >> 1;
    const bool isP = (z & 1) == 0;
    const float* W1 = st ? tW1 : sW1;
    const float* B1 = st ? tb1 : sb1;
    const int n0 = blockIdx.x * 128;
    const int tid = threadIdx.x, ty = tid >> 4, tx = tid & 15;
    ull acc[8][4];
#pragma unroll
    for (int i = 0; i < 8; i++)
#pragma unroll
        for (int j = 0; j < 4; j++) acc[i][j] = 0ull;

    for (int kc = 0; kc < CDIM; kc += 32) {
        __syncthreads();
        for (int idx = tid; idx < 128 * 32; idx += 256) {
            int r = idx >> 5, kk = idx & 31;
            Xs[kk][r] = x[(size_t)(n0 + r) * CDIM + kc + kk];
        }
        for (int idx = tid; idx < 32 * HDIM; idx += 256) {
            int kk = idx >> 7, col = idx & 127;
            int kr = kc + kk;
            float w = W1[(size_t)(CDIM + kr) * HDIM + col];
            if (isP) w = W1[(size_t)kr * HDIM + col] - w;
            Ws[kk][col] = w;
        }
        __syncthreads();
#pragma unroll 8
        for (int kk = 0; kk < 32; kk++)
            micro_step(&Xs[kk][0], &Ws[kk][0], ty * 8, tx * 8, acc);
    }
    float outv[8][8];
    unpack_acc(acc, outv);
    float* O = isP ? g_p[st] : g_q[st];
    float bj[8];
#pragma unroll
    for (int j = 0; j < 8; j++) bj[j] = isP ? B1[tx * 8 + j] : 0.f;
#pragma unroll
    for (int i = 0; i < 8; i++) {
        size_t row = (size_t)(n0 + ty * 8 + i) * HDIM + tx * 8;
        *(float4*)&O[row]     = make_float4(outv[i][0] + bj[0], outv[i][1] + bj[1],
                                            outv[i][2] + bj[2], outv[i][3] + bj[3]);
        *(float4*)&O[row + 4] = make_float4(outv[i][4] + bj[4], outv[i][5] + bj[5],
                                            outv[i][6] + bj[6], outv[i][7] + bj[7]);
    }
}

// ---------------------------------------------------------------------------
// 5: BN1 statistics
// ---------------------------------------------------------------------------
__global__ void k_bn1stats() {
    const int h = threadIdx.x;
    const int node0 = blockIdx.x * 32;
    float s0 = 0.f, q0 = 0.f, s1 = 0.f, q1 = 0.f;
    for (int nl = 0; nl < 32; nl++) {
        int n = node0 + nl;
        float p0 = g_p[0][(size_t)n * HDIM + h];
        float p1 = g_p[1][(size_t)n * HDIM + h];
        for (int k = 0; k < KNEIGH; k++) {
            int j = g_idx[(size_t)n * KNEIGH + k];
            float a = p0 + g_q[0][(size_t)j * HDIM + h];
            float b = p1 + g_q[1][(size_t)j * HDIM + h];
            s0 += a; q0 += a * a;
            s1 += b; q1 += b * b;
        }
    }
    atomicAdd(&g_bn1_sum[0][h], s0); atomicAdd(&g_bn1_sq[0][h], q0);
    atomicAdd(&g_bn1_sum[1][h], s1); atomicAdd(&g_bn1_sq[1][h], q1);
}

// ---------------------------------------------------------------------------
// 6: BN finalize
// ---------------------------------------------------------------------------
__global__ void k_bnfin(int which, int st, const float* __restrict__ g,
                        const float* __restrict__ be, float invN) {
    int h = threadIdx.x;
    float s, q;
    if (which == 0)      { s = g_bn1_sum[st][h]; q = g_bn1_sq[st][h]; }
    else if (which == 1) { s = g_bn2_sum[st][h]; q = g_bn2_sq[st][h]; }
    else                 { s = g_bnF_sum[h];     q = g_bnF_sq[h]; }
    float m   = s * invN;
    float var = fmaxf(q * invN - m * m, 0.f);
    float a   = g[h] * rsqrtf(var + BN_EPS);
    float c   = be[h] - m * a;
    if (which == 0)      { g_a1[st][h] = a; g_c1[st][h] = c; }
    else if (which == 1) { g_a2[st][h] = a; g_c2[st][h] = c; }
    else                 { g_aF[h] = a;     g_cF[h] = c; }
}

// ---------------------------------------------------------------------------
// 6b: prep W2^T split bf16 hi/lo, row-major [n][k] pitch BKP (raw smem image)
// ---------------------------------------------------------------------------
__global__ void k_w2prep(const float* __restrict__ sW2, const float* __restrict__ tW2) {
    const int st = blockIdx.x;
    const float* W2 = st ? tW2 : sW2;
    __nv_bfloat16* H = (__nv_bfloat16*)g_w2t_hi[st];
    __nv_bfloat16* L = (__nv_bfloat16*)g_w2t_lo[st];
    for (int lin = threadIdx.x; lin < HDIM * HDIM; lin += blockDim.x) {
        int n = lin & 127, k = lin >> 7;
        float w = W2[(size_t)k * HDIM + n];
        __nv_bfloat16 hi = __float2bfloat16_rn(w);
        __nv_bfloat16 lo = __float2bfloat16_rn(w - __bfloat162float(hi));
        H[n * BKP + k] = hi;
        L[n * BKP + k] = lo;
    }
}

// ---------------------------------------------------------------------------
// 7: edge GEMM on mma.sync bf16 (split hi/lo, 3 passes). Persistent blocks:
//    each block loads W2 tiles ONCE and loops over EDGE_GROUPS node-groups
//    (amortizes 69.6KB B-copy that previously repeated per 8-node block).
// ---------------------------------------------------------------------------
__global__ __launch_bounds__(256)
void k_edge_mma(const float* __restrict__ sb2v, const float* __restrict__ tb2v) {
    extern __shared__ __nv_bfloat16 dsm[];
    __shared__ int   sidx[128];
    __shared__ float s_sum[128], s_sq[128], b2s[128];

    const int st = blockIdx.z;
    const int tid = threadIdx.x;
    const int wid = tid >> 5, lane = tid & 31;
    const int warp_m = wid & 3, warp_n = wid >> 2;
    const float* B2 = st ? tb2v : sb2v;
    const float* P  = g_p[st];
    const float* Q  = g_q[st];
    const float* A1 = g_a1[st];
    const float* C1 = g_c1[st];

    __nv_bfloat16* Ahi = dsm;
    __nv_bfloat16* Alo = Ahi + HDIM * BKP;
    __nv_bfloat16* Bhi = Alo + HDIM * BKP;
    __nv_bfloat16* Blo = Bhi + HDIM * BKP;

    if (tid < 128) {
        s_sum[tid] = 0.f; s_sq[tid] = 0.f;
        b2s[tid]   = B2[tid];
    }

    // B tiles: loaded once per block (persistent over EDGE_GROUPS groups)
    {
        const uint4* srch = (const uint4*)g_w2t_hi[st];
        const uint4* srcl = (const uint4*)g_w2t_lo[st];
        uint4* dsth = (uint4*)Bhi;
        uint4* dstl = (uint4*)Blo;
        for (int i = tid; i < W2T_BYTES / 16; i += 256) { dsth[i] = srch[i]; dstl[i] = srcl[i]; }
    }

    const int arow = warp_m * 32 + (lane >> 2);
    const int acol = (lane & 3) * 2;
    const int brow = warp_n * 64 + (lane >> 2);

    for (int g = 0; g < EDGE_GROUPS; g++) {
        const int node0 = (blockIdx.x * EDGE_GROUPS + g) * 8;

        __syncthreads();   // prev mainloop done reading A; sidx safe to overwrite
        if (tid < 128) sidx[tid] = g_idx[(size_t)node0 * KNEIGH + tid];
        __syncthreads();

        // A tile: gather + BN1 + ReLU + hi/lo split
        {
            int e = tid >> 1, half = tid & 1, k0 = half * 64;
            int n = node0 + (e >> 4);
            int j = sidx[e];
            const float4* Pr = (const float4*)(P + (size_t)n * HDIM + k0);
            const float4* Qr = (const float4*)(Q + (size_t)j * HDIM + k0);
            const float4* Av = (const float4*)(A1 + k0);
            const float4* Cv = (const float4*)(C1 + k0);
            __nv_bfloat16* ah = Ahi + e * BKP + k0;
            __nv_bfloat16* al = Alo + e * BKP + k0;
#pragma unroll
            for (int i = 0; i < 16; i++) {
                float4 pv = Pr[i], qv = Qr[i], av = Av[i], cv = Cv[i];
                float z0 = fmaxf(fmaf(av.x, pv.x + qv.x, cv.x), 0.f);
                float z1 = fmaxf(fmaf(av.y, pv.y + qv.y, cv.y), 0.f);
                float z2 = fmaxf(fmaf(av.z, pv.z + qv.z, cv.z), 0.f);
                float z3 = fmaxf(fmaf(av.w, pv.w + qv.w, cv.w), 0.f);
                __nv_bfloat162 h0, l0, h1, l1;
                split2(z0, z1, h0, l0); split2(z2, z3, h1, l1);
                *(__nv_bfloat162*)(ah + i * 4)     = h0;
                *(__nv_bfloat162*)(ah + i * 4 + 2) = h1;
                *(__nv_bfloat162*)(al + i * 4)     = l0;
                *(__nv_bfloat162*)(al + i * 4 + 2) = l1;
            }
        }
        __syncthreads();

        float acc[2][8][4];
#pragma unroll
        for (int mt = 0; mt < 2; mt++)
#pragma unroll
            for (int nt = 0; nt < 8; nt++)
#pragma unroll
                for (int r = 0; r < 4; r++) acc[mt][nt][r] = 0.f;

#pragma unroll
        for (int pass = 0; pass < 3; pass++) {
            const __nv_bfloat16* As = (pass == 2) ? Alo : Ahi;
            const __nv_bfloat16* Bs = (pass == 1) ? Blo : Bhi;
#pragma unroll
            for (int k8 = 0; k8 < 8; k8++) {
                int kk = k8 * 16 + acol;
                uint32_t afr[2][4];
#pragma unroll
                for (int mt = 0; mt < 2; mt++) {
                    const __nv_bfloat16* ap = As + (size_t)(arow + mt * 16) * BKP + kk;
                    afr[mt][0] = *(const uint32_t*)(ap);
                    afr[mt][1] = *(const uint32_t*)(ap + 8 * BKP);
                    afr[mt][2] = *(const uint32_t*)(ap + 8);
                    afr[mt][3] = *(const uint32_t*)(ap + 8 * BKP + 8);
                }
                uint32_t bfr[8][2];
#pragma unroll
                for (int nt = 0; nt < 8; nt++) {
                    const __nv_bfloat16* bp = Bs + (size_t)(brow + nt * 8) * BKP + kk;
                    bfr[nt][0] = *(const uint32_t*)(bp);
                    bfr[nt][1] = *(const uint32_t*)(bp + 8);
                }
#pragma unroll
                for (int mt = 0; mt < 2; mt++)
#pragma unroll
                    for (int nt = 0; nt < 8; nt++)
                        mma16816(acc[mt][nt], afr[mt], bfr[nt]);
            }
        }

        // epilogue: each m-tile (16 rows) = one node's 16 edges
#pragma unroll
        for (int mt = 0; mt < 2; mt++) {
            const int node = node0 + warp_m * 2 + mt;
#pragma unroll
            for (int nt = 0; nt < 8; nt++) {
                const int col = warp_n * 64 + nt * 8 + (lane & 3) * 2;
                float bb0 = b2s[col], bb1 = b2s[col + 1];
                float v0 = acc[mt][nt][0] + bb0, v1 = acc[mt][nt][1] + bb1;
                float v2 = acc[mt][nt][2] + bb0, v3 = acc[mt][nt][3] + bb1;
                float mx0 = fmaxf(v0, v2), mx1 = fmaxf(v1, v3);
                float mn0 = fminf(v0, v2), mn1 = fminf(v1, v3);
                float sm0 = v0 + v2,       sm1 = v1 + v3;
                float sq0 = v0 * v0 + v2 * v2, sq1 = v1 * v1 + v3 * v3;
#pragma unroll
                for (int off = 4; off <= 16; off <<= 1) {
                    mx0 = fmaxf(mx0, __shfl_xor_sync(0xffffffffu, mx0, off));
                    mx1 = fmaxf(mx1, __shfl_xor_sync(0xffffffffu, mx1, off));
                    mn0 = fminf(mn0, __shfl_xor_sync(0xffffffffu, mn0, off));
                    mn1 = fminf(mn1, __shfl_xor_sync(0xffffffffu, mn1, off));
                    sm0 += __shfl_xor_sync(0xffffffffu, sm0, off);
                    sm1 += __shfl_xor_sync(0xffffffffu, sm1, off);
                    sq0 += __shfl_xor_sync(0xffffffffu, sq0, off);
                    sq1 += __shfl_xor_sync(0xffffffffu, sq1, off);
                }
                if (lane < 4) {
                    size_t o = (size_t)node * HDIM + col;
                    g_aggmax[st][o]     = mx0;
                    g_aggmax[st][o + 1] = mx1;
                    g_aggmin[st][o]     = mn0;
                    g_aggmin[st][o + 1] = mn1;
                    atomicAdd(&s_sum[col], sm0);  atomicAdd(&s_sum[col + 1], sm1);
                    atomicAdd(&s_sq[col],  sq0);  atomicAdd(&s_sq[col + 1],  sq1);
                }
            }
        }
    }
    __syncthreads();
    if (tid < 128) {
        atomicAdd(&g_bn2_sum[st][tid], s_sum[tid]);
        atomicAdd(&g_bn2_sq[st][tid], s_sq[tid]);
    }
}

// ---------------------------------------------------------------------------
// 8: final GEMM
// ---------------------------------------------------------------------------
__global__ __launch_bounds__(256) void k_final(const float* __restrict__ fW, const float* __restrict__ fb) {
    __shared__ float Fs[32][LDW];
    __shared__ float Ws[32][LDW];
    __shared__ float s_sum[HDIM], s_sq[HDIM];
    const int n0 = blockIdx.x * 128;
    const int tid = threadIdx.x, ty = tid >> 4, tx = tid & 15;
    if (tid < 128) { s_sum[tid] = 0.f; s_sq[tid] = 0.f; }
    ull acc[8][4];
#pragma unroll
    for (int i = 0; i < 8; i++)
#pragma unroll
        for (int j = 0; j < 4; j++) acc[i][j] = 0ull;

    for (int kc = 0; kc < 2 * HDIM; kc += 32) {
        __syncthreads();
        for (int idx = tid; idx < 128 * 32; idx += 256) {
            int nl = idx >> 5, kk = idx & 31;
            int kf = kc + kk;
            int st = kf >> 7, ch = kf & 127;
            float a2 = g_a2[st][ch], c2 = g_c2[st][ch];
            size_t o = (size_t)(n0 + nl) * HDIM + ch;
            float v = (a2 >= 0.f) ? g_aggmax[st][o] : g_aggmin[st][o];
            Fs[kk][nl] = fmaxf(fmaf(a2, v, c2), 0.f);
        }
        for (int idx = tid; idx < 32 * HDIM; idx += 256) {
            int kk = idx >> 7, col = idx & 127;
            Ws[kk][col] = fW[(size_t)(kc + kk) * HDIM + col];
        }
        __syncthreads();
#pragma unroll 8
        for (int kk = 0; kk < 32; kk++)
            micro_step(&Fs[kk][0], &Ws[kk][0], ty * 8, tx * 8, acc);
    }
    float outv[8][8];
    unpack_acc(acc, outv);
    float bj[8];
#pragma unroll
    for (int j = 0; j < 8; j++) bj[j] = fb[tx * 8 + j];
#pragma unroll
    for (int i = 0; i < 8; i++)
#pragma unroll
        for (int j = 0; j < 8; j++) outv[i][j] += bj[j];
#pragma unroll
    for (int i = 0; i < 8; i++) {
        size_t row = (size_t)(n0 + ty * 8 + i) * HDIM + tx * 8;
        *(float4*)&g_hF[row]     = make_float4(outv[i][0], outv[i][1], outv[i][2], outv[i][3]);
        *(float4*)&g_hF[row + 4] = make_float4(outv[i][4], outv[i][5], outv[i][6], outv[i][7]);
    }
#pragma unroll
    for (int j = 0; j < 8; j++) {
        float cs = 0.f, cq = 0.f;
#pragma unroll
        for (int i = 0; i < 8; i++) { float v = outv[i][j]; cs += v; cq += v * v; }
        cs += __shfl_xor_sync(0xffffffffu, cs, 16);
        cq += __shfl_xor_sync(0xffffffffu, cq, 16);
        if ((ty & 1) == 0) {
            int col = tx * 8 + j;
            atomicAdd(&s_sum[col], cs);
            atomicAdd(&s_sq[col], cq);
        }
    }
    __syncthreads();
    if (tid < 128) {
        atomicAdd(&g_bnF_sum[tid], s_sum[tid]);
        atomicAdd(&g_bnF_sq[tid], s_sq[tid]);
    }
}

// ---------------------------------------------------------------------------
// 9: output elementwise
// ---------------------------------------------------------------------------
__global__ void k_out(float* __restrict__ out) {
    int idx = blockIdx.x * 256 + threadIdx.x;
    int col = idx & 127;
    out[idx] = fmaxf(fmaf(g_aF[col], g_hF[idx], g_cF[col]), 0.f);
}

// ---------------------------------------------------------------------------
// launcher
// ---------------------------------------------------------------------------
extern "C" void kernel_launch(void* const* d_in, const int* in_sizes, int n_in,
                              void* d_out, int out_size) {
    (void)in_sizes; (void)n_in; (void)out_size;
    const float* x     = (const float*)d_in[0];
    const float* s_W1  = (const float*)d_in[2];
    const float* s_b1  = (const float*)d_in[3];
    const float* s_g1  = (const float*)d_in[4];
    const float* s_be1 = (const float*)d_in[5];
    const float* s_W2  = (const float*)d_in[6];
    const float* s_b2  = (const float*)d_in[7];
    const float* s_g2  = (const float*)d_in[8];
    const float* s_be2 = (const float*)d_in[9];
    const float* t_W1  = (const float*)d_in[10];
    const float* t_b1  = (const float*)d_in[11];
    const float* t_g1  = (const float*)d_in[12];
    const float* t_be1 = (const float*)d_in[13];
    const float* t_W2  = (const float*)d_in[14];
    const float* t_b2  = (const float*)d_in[15];
    const float* t_g2  = (const float*)d_in[16];
    const float* t_be2 = (const float*)d_in[17];
    const float* f_W   = (const float*)d_in[18];
    const float* f_b   = (const float*)d_in[19];
    const float* f_g   = (const float*)d_in[20];
    const float* f_be  = (const float*)d_in[21];
    float* out = (float*)d_out;

    const float invE  = 1.f / (float)EDGES;
    const float invNT = 1.f / (float)NT;

    cudaFuncSetAttribute(k_edge_mma, cudaFuncAttributeMaxDynamicSharedMemorySize, EDGE_SMEM);

    k_zero<<<1, 128>>>();
    k_sq<<<NT / 8, 256>>>(x);
    k_d2<<<dim3(NNODE / 128, NNODE / 128, BBATCH), 256>>>(x);
    k_topk<<<NT / TKW, 32 * TKW>>>();
    k_pq<<<dim3(NT / 128, 1, 4), 256>>>(x, s_W1, s_b1, t_W1, t_b1);
    k_bn1stats<<<NT / 32, 128>>>();
    k_bnfin<<<1, 128>>>(0, 0, s_g1, s_be1, invE);
    k_bnfin<<<1, 128>>>(0, 1, t_g1, t_be1, invE);
    k_w2prep<<<2, 256>>>(s_W2, t_W2);
    k_edge_mma<<<dim3(EDGE_BLOCKS, 1, 2), 256, EDGE_SMEM>>>(s_b2, t_b2);
    k_bnfin<<<1, 128>>>(1, 0, s_g2, s_be2, invE);
    k_bnfin<<<1, 128>>>(1, 1, t_g2, t_be2, invE);
    k_final<<<NT / 128, 256>>>(f_W, f_b);
    k_bnfin<<<1, 128>>>(2, 0, f_g, f_be, invNT);
    k_out<<<(NT * HDIM) / 256, 256>>>(out);
}